// round 14
// baseline (speedup 1.0000x reference)
#include <cuda_runtime.h>
#include <cuda_fp16.h>
#include <math.h>
#include <stdint.h>

#define NN 10000
#define EE 160000
#define CC 128

// ---------------- scratch ------------------------------------------------------
__device__ float  g_h   [NN*CC];
__device__ float  g_agg [9*NN*CC];          // zero-init at load; re-cleared by contract_k
__device__ float  g_svt [9*NN*CC];
__device__ float  g_B   [4*NN*CC];
__device__ float  g_hout[4*NN*CC];
__device__ float  g_zr  [NN*64];            // gate per node
__device__ int    g_cnt [NN+1];             // zero-init; re-zeroed by final_k
__device__ int    g_perm[EE];
__device__ __half g_wt  [6*2*128*136];
__device__ __half g_wr1t[2*64*136];
__device__ __half g_wr2t[2*384*72];         // pre-scaled by 1/16
__device__ __half g_w1t [2*64*136];
__device__ __half g_w2t [2*128*72];

// ---------------- helpers -------------------------------------------------------
__device__ __forceinline__ uint32_t s2u(const void* p) {
    uint32_t a;
    asm("{ .reg .u64 t; cvta.to.shared.u64 t, %1; cvt.u32.u64 %0, t; }" : "=r"(a) : "l"(p));
    return a;
}
__device__ __forceinline__ void ldmx4(uint32_t& r0, uint32_t& r1, uint32_t& r2, uint32_t& r3,
                                      uint32_t a) {
    asm volatile("ldmatrix.sync.aligned.m8n8.x4.shared.b16 {%0,%1,%2,%3}, [%4];"
                 : "=r"(r0), "=r"(r1), "=r"(r2), "=r"(r3) : "r"(a));
}
__device__ __forceinline__ void mma4(float c[4], uint32_t a0, uint32_t a1, uint32_t a2,
                                     uint32_t a3, uint32_t b0, uint32_t b1) {
    asm volatile("mma.sync.aligned.m16n8k16.row.col.f32.f16.f16.f32 "
                 "{%0,%1,%2,%3},{%4,%5,%6,%7},{%8,%9},{%0,%1,%2,%3};"
                 : "+f"(c[0]), "+f"(c[1]), "+f"(c[2]), "+f"(c[3])
                 : "r"(a0), "r"(a1), "r"(a2), "r"(a3), "r"(b0), "r"(b1));
}
__device__ __forceinline__ uint32_t afa(uint32_t base, int lane, int mrow, int kb, int sh) {
    int row = mrow + (lane & 15);
    int k = kb + ((lane >> 4) << 3);
    return base + (uint32_t)(row * sh + k) * 2;
}
__device__ __forceinline__ uint32_t bfa(uint32_t base, int lane, int nb, int kb, int sh) {
    int n = nb + (lane & 7) + ((lane >> 4) << 3);
    int k = kb + (((lane >> 3) & 1) << 3);
    return base + (uint32_t)(n * sh + k) * 2;
}
__device__ __forceinline__ void red4(float* p, float4 v) {
    asm volatile("red.global.add.v4.f32 [%0], {%1,%2,%3,%4};"
                 :: "l"(p), "f"(v.x), "f"(v.y), "f"(v.z), "f"(v.w) : "memory");
}
__device__ __forceinline__ void mma_pair(float Ce[4], float Co[4],
    uint32_t ah0,uint32_t ah1,uint32_t ah2,uint32_t ah3,
    uint32_t al0,uint32_t al1,uint32_t al2,uint32_t al3,
    uint32_t bh0,uint32_t bh1,uint32_t bh2,uint32_t bh3,
    uint32_t bl0,uint32_t bl1,uint32_t bl2,uint32_t bl3)
{
    mma4(Ce, ah0, ah1, ah2, ah3, bh0, bh1);
    mma4(Co, ah0, ah1, ah2, ah3, bh2, bh3);
    mma4(Ce, al0, al1, al2, al3, bh0, bh1);
    mma4(Co, al0, al1, al2, al3, bh2, bh3);
    mma4(Ce, ah0, ah1, ah2, ah3, bl0, bl1);
    mma4(Co, ah0, ah1, ah2, ah3, bl2, bl3);
}
__device__ __forceinline__ void cvt4(__half* Hp, __half* Lp, int idx, float4 v) {
    __half h0 = __float2half_rn(v.x), h1 = __float2half_rn(v.y);
    __half h2 = __float2half_rn(v.z), h3 = __float2half_rn(v.w);
    ((__half2*)(Hp + idx))[0] = __halves2half2(h0, h1);
    ((__half2*)(Hp + idx))[1] = __halves2half2(h2, h3);
    ((__half2*)(Lp + idx))[0] = __halves2half2(__float2half_rn(v.x - __half2float(h0)),
                                               __float2half_rn(v.y - __half2float(h1)));
    ((__half2*)(Lp + idx))[1] = __halves2half2(__float2half_rn(v.z - __half2float(h2)),
                                               __float2half_rn(v.w - __half2float(h3)));
}

// ---------------- launch 0: weight prep + rcv histogram -------------------------
__global__ void prep_all(const float* W_up, const float* Wl0, const float* Wl1,
                         const float* Wl2, const float* P0, const float* P1,
                         const float* Wr1, const float* Wr2,
                         const float* W1, const float* W2,
                         const int* edge_index, int E)
{
    int w = blockIdx.y;
    if (w == 10) {
        for (int e = blockIdx.x * blockDim.x + threadIdx.x; e < E;
             e += gridDim.x * blockDim.x)
            atomicAdd(&g_cnt[edge_index[E + e]], 1);
        return;
    }
    const float* src; __half* dst; int K, Nr, ldw, stride; float sc = 1.f;
    const int TS = 2 * 128 * 136;
    switch (w) {
        case 0: src = W_up; dst = g_wt;        K=128; Nr=128; ldw=128; stride=136; break;
        case 1: src = Wl0;  dst = g_wt + 1*TS; K=128; Nr=128; ldw=128; stride=136; break;
        case 2: src = Wl1;  dst = g_wt + 2*TS; K=128; Nr=128; ldw=128; stride=136; break;
        case 3: src = Wl2;  dst = g_wt + 3*TS; K=128; Nr=128; ldw=128; stride=136; break;
        case 4: src = P0;   dst = g_wt + 4*TS; K=128; Nr=128; ldw=128; stride=136; break;
        case 5: src = P1;   dst = g_wt + 5*TS; K=128; Nr=128; ldw=128; stride=136; break;
        case 6: src = Wr1;  dst = g_wr1t;      K=128; Nr= 64; ldw= 64; stride=136; break;
        case 7: src = Wr2;  dst = g_wr2t;      K= 64; Nr=384; ldw=384; stride= 72;
                sc = 0.0625f; break;
        case 8: src = W1;   dst = g_w1t;       K=128; Nr= 64; ldw= 64; stride=136; break;
        default:src = W2;   dst = g_w2t;       K= 64; Nr=128; ldw=128; stride= 72; break;
    }
    int i = blockIdx.x * blockDim.x + threadIdx.x;
    if (i >= K * Nr) return;
    int n = i / K, k = i % K;
    float v = src[(size_t)k * ldw + n] * sc;
    __half h = __float2half_rn(v);
    dst[(size_t)n * stride + k] = h;
    dst[(size_t)Nr * stride + (size_t)n * stride + k] = __float2half_rn(v - __half2float(h));
}

// ---------------- launch 1: exclusive scan of histogram -------------------------
__global__ void scan_k(int N)
{
    __shared__ int buf[1024];
    __shared__ int carry;
    int t = threadIdx.x;
    if (t == 0) carry = 0;
    __syncthreads();
    for (int base = 0; base < N; base += 1024) {
        int v = (base + t < N) ? g_cnt[base + t] : 0;
        buf[t] = v; __syncthreads();
#pragma unroll
        for (int off = 1; off < 1024; off <<= 1) {
            int x = (t >= off) ? buf[t - off] : 0;
            __syncthreads();
            buf[t] += x;
            __syncthreads();
        }
        int incl = buf[t];
        if (base + t < N) g_cnt[base + t] = carry + incl - v;
        __syncthreads();
        if (t == 1023) carry += incl;
        __syncthreads();
    }
}

// ---------------- node-GEMM v3: 64-row x 64-col tiles, 69.6KB -> 3 CTA/SM --------
// smem: Ah 0..17408, Al ..34816, Bh 34816..52224, Bl ..69632
__device__ __forceinline__ void node_gemm(const float* A, float* O, int M, int tile,
                                          int tiles, char* smem, int bx, int gx, int nh)
{
    __half* Ah = (__half*)smem;
    __half* Al = (__half*)(smem + 17408);
    uint32_t sb = s2u(smem);
    int tid = threadIdx.x, wid = tid >> 5, lane = tid & 31;
    int rw = wid & 3, cw = wid >> 2;      // 4 row-warps x 2 col-warps
    int mrow = rw * 16;

    {   // W copy: 64 n-rows (nh half) x 136 stride, hi+lo: 1088 uint4 each
        const uint4* sh4 = (const uint4*)(g_wt + (size_t)tile * (2*128*136)
                                          + (size_t)nh * 64 * 136);
        const uint4* sl4 = (const uint4*)(g_wt + (size_t)tile * (2*128*136)
                                          + (size_t)128 * 136 + (size_t)nh * 64 * 136);
        uint4* dh = (uint4*)(smem + 34816);
        uint4* dl = (uint4*)(smem + 52224);
        for (int i = tid; i < 1088; i += 256) { dh[i] = sh4[i]; dl[i] = sl4[i]; }
    }
    uint32_t ab_h = sb, ab_l = sb + 17408, bb_h = sb + 34816, bb_l = sb + 52224;
    int rr = tid >> 2, q4 = tid & 3;

    for (int tl = bx; tl < tiles; tl += gx) {
        int bm = tl * 64;
        bool valid = (bm + rr) < M;
        const float* Arow = A + (size_t)(bm + rr) * 128;
#pragma unroll
        for (int q = 0; q < 8; q++) {
            float4 v = valid ? ((const float4*)Arow)[q4 * 8 + q]
                             : make_float4(0.f, 0.f, 0.f, 0.f);
            cvt4(Ah, Al, rr * 136 + q4 * 32 + q * 4, v);
        }
        __syncthreads();

        float C[4][4];
#pragma unroll
        for (int i = 0; i < 4; i++)
#pragma unroll
            for (int j = 0; j < 4; j++) C[i][j] = 0.f;

        for (int kb = 0; kb < 128; kb += 16) {
            uint32_t ah0, ah1, ah2, ah3, al0, al1, al2, al3;
            ldmx4(ah0, ah1, ah2, ah3, afa(ab_h, lane, mrow, kb, 136));
            ldmx4(al0, al1, al2, al3, afa(ab_l, lane, mrow, kb, 136));
#pragma unroll
            for (int nt2 = 0; nt2 < 2; nt2++) {
                uint32_t bh0, bh1, bh2, bh3, bl0, bl1, bl2, bl3;
                int nb = cw * 32 + nt2 * 16;
                ldmx4(bh0, bh1, bh2, bh3, bfa(bb_h, lane, nb, kb, 136));
                ldmx4(bl0, bl1, bl2, bl3, bfa(bb_l, lane, nb, kb, 136));
                mma_pair(C[2*nt2], C[2*nt2+1], ah0,ah1,ah2,ah3, al0,al1,al2,al3,
                         bh0,bh1,bh2,bh3, bl0,bl1,bl2,bl3);
            }
        }

        int r0 = bm + mrow + (lane >> 2);
        int c0 = nh * 64 + cw * 32 + (lane & 3) * 2;
        bool v0 = r0 < M, v1 = (r0 + 8) < M;
#pragma unroll
        for (int nt = 0; nt < 4; nt++) {
            int col = c0 + nt * 8;
            if (v0) *(float2*)(O + (size_t)r0 * 128 + col) = make_float2(C[nt][0], C[nt][1]);
            if (v1) *(float2*)(O + (size_t)(r0 + 8) * 128 + col) = make_float2(C[nt][2], C[nt][3]);
        }
        __syncthreads();
    }
}

// ---------------- launch 2: y0 = permutation scatter, y1/2 = h GEMM halves ------
__global__ void __launch_bounds__(256, 3)
permh(const int* __restrict__ edge_index, const float* __restrict__ node_feats,
      int E, int M, int mt)
{
    extern __shared__ char smem[];
    if (blockIdx.y == 0) {
        for (int e = blockIdx.x * blockDim.x + threadIdx.x; e < E;
             e += gridDim.x * blockDim.x) {
            int rcv = edge_index[E + e];
            int pos = atomicAdd(&g_cnt[rcv], 1);
            g_perm[pos] = e;
        }
        return;
    }
    node_gemm(node_feats, g_h, M, 0, mt, smem, blockIdx.x, gridDim.x, blockIdx.y - 1);
}

// ---------------- launches 4/6: svt = agg@Wl, hout = B@P (n-split) --------------
__global__ void __launch_bounds__(256, 3)
mma128(const float* __restrict__ A0, float* __restrict__ O0, int M, int phase, int mt)
{
    extern __shared__ char smem[];
    int comp = blockIdx.y >> 1;
    int nh = blockIdx.y & 1;
    int tile = (phase == 1) ? ((comp == 0) ? 1 : (comp < 4 ? 2 : 3))
                            : ((comp == 0) ? 4 : 5);
    node_gemm(A0 + (size_t)comp * M * 128, O0 + (size_t)comp * M * 128,
              M, tile, mt, smem, blockIdx.x, gridDim.x, nh);
}

// ---------------- launch 3: fused edge kernel (unchanged from R12) ---------------
__global__ void __launch_bounds__(256, 3)
edge_fused(const float* __restrict__ vectors, const int* __restrict__ edge_index,
           const float* __restrict__ edge_feats, const float* __restrict__ lengths,
           const float* __restrict__ wlast, const float* __restrict__ bias,
           int E, int N)
{
    extern __shared__ char smc[];
    uint32_t sb = s2u(smc);
    __half* efAh = (__half*)smc;
    __half* efAl = (__half*)(smc + 17408);
    float* wl_sm = (float*)(smc + 69632);
    float* b_sm  = (float*)(smc + 69888);
    float* Ys    = (float*)(smc + 70144);
    int* snd_s   = (int*)(smc + 72192);
    int* rcv_s   = (int*)(smc + 72448);
    float* len_s = (float*)(smc + 72704);
    float* stage = (float*)(smc + 18432);
    int tid = threadIdx.x, wid = tid >> 5, lane = tid & 31;
    int e0 = blockIdx.x * 64;
    int rw = wid & 3, cw = wid >> 2;
    int mrow = rw * 16;

    if (tid < 64) { wl_sm[tid] = wlast[tid]; b_sm[tid] = bias[tid]; }
    {   const uint4* s = (const uint4*)g_wr1t;
        uint4* d = (uint4*)(smc + 34816);
        for (int i = tid; i < 2176; i += 256) d[i] = s[i];
    }
    {   int r = tid >> 2, q4 = tid & 3;
        bool valid = (e0 + r) < E;
        const float* Arow = edge_feats + (valid ? (size_t)g_perm[e0 + r] * 128 : 0);
#pragma unroll
        for (int q = 0; q < 8; q++) {
            float4 v = valid ? ((const float4*)Arow)[q4 * 8 + q]
                             : make_float4(0.f, 0.f, 0.f, 0.f);
            cvt4(efAh, efAl, r * 136 + q4 * 32 + q * 4, v);
        }
    }
    if (tid < 64) {
        int e = e0 + tid;
        int snd = 0, rcv = 0;
        float vx = 0.f, vy = 1.f, vz = 0.f, ln = 0.f;
        if (e < E) {
            int pe = g_perm[e];
            snd = edge_index[pe]; rcv = edge_index[E + pe];
            vx = vectors[3*pe]; vy = vectors[3*pe+1]; vz = vectors[3*pe+2];
            ln = lengths[pe];
        }
        snd_s[tid] = snd; rcv_s[tid] = rcv; len_s[tid] = ln;
        float inv = 1.f / (sqrtf(vx*vx + vy*vy + vz*vz) + 1e-9f);
        float ux = vx*inv, uy = vy*inv, uz = vz*inv;
        const float S3 = 1.7320508075688772f, S15 = 3.8729833462074170f;
        const float S15H = 1.9364916731037085f, S5H = 1.1180339887498949f;
        float* y = Ys + tid * 8;
        y[0] = S3*ux; y[1] = S3*uy; y[2] = S3*uz;
        y[3] = S15*ux*uy; y[4] = S15*uy*uz; y[5] = S5H*(3.f*uz*uz - 1.f);
        y[6] = S15*ux*uz; y[7] = S15H*(ux*ux - uy*uy);
    }
    __syncthreads();

    float Cz[4][4];
#pragma unroll
    for (int i = 0; i < 4; i++)
#pragma unroll
        for (int j = 0; j < 4; j++) Cz[i][j] = 0.f;
    {
        uint32_t ab_h = sb, ab_l = sb + 17408, bb_h = sb + 34816, bb_l = sb + 52224;
        for (int kb = 0; kb < 128; kb += 16) {
            uint32_t ah0, ah1, ah2, ah3, al0, al1, al2, al3;
            ldmx4(ah0, ah1, ah2, ah3, afa(ab_h, lane, mrow, kb, 136));
            ldmx4(al0, al1, al2, al3, afa(ab_l, lane, mrow, kb, 136));
#pragma unroll
            for (int nt2 = 0; nt2 < 2; nt2++) {
                uint32_t bh0, bh1, bh2, bh3, bl0, bl1, bl2, bl3;
                int nb = cw * 32 + nt2 * 16;
                ldmx4(bh0, bh1, bh2, bh3, bfa(bb_h, lane, nb, kb, 136));
                ldmx4(bl0, bl1, bl2, bl3, bfa(bb_l, lane, nb, kb, 136));
                mma_pair(Cz[2*nt2], Cz[2*nt2+1], ah0,ah1,ah2,ah3, al0,al1,al2,al3,
                         bh0,bh1,bh2,bh3, bl0,bl1,bl2,bl3);
            }
        }
    }
    __syncthreads();

    {
        int r0 = mrow + (lane >> 2);
        int c0 = cw * 32 + (lane & 3) * 2;
        float len0 = len_s[r0];
        float len1 = len_s[r0 + 8];
#pragma unroll
        for (int nt = 0; nt < 4; nt++) {
            int col = c0 + nt * 8;
            float wl0 = wl_sm[col], wl1 = wl_sm[col + 1];
            float bb0 = b_sm[col],  bb1 = b_sm[col + 1];
            float f0 = Cz[nt][0] + len0 * wl0 + bb0;
            float f1 = Cz[nt][1] + len0 * wl1 + bb1;
            float f2 = Cz[nt][2] + len1 * wl0 + bb0;
            float f3 = Cz[nt][3] + len1 * wl1 + bb1;
            f0 = f0 / (1.f + __expf(-f0));
            f1 = f1 / (1.f + __expf(-f1));
            f2 = f2 / (1.f + __expf(-f2));
            f3 = f3 / (1.f + __expf(-f3));
            __half h0 = __float2half_rn(f0), h1 = __float2half_rn(f1);
            __half h2 = __float2half_rn(f2), h3 = __float2half_rn(f3);
            *(__half2*)(smc + r0 * 144 + col * 2) = __halves2half2(h0, h1);
            *(__half2*)(smc + (r0 + 8) * 144 + col * 2) = __halves2half2(h2, h3);
            *(__half2*)(smc + 9216 + r0 * 144 + col * 2) =
                __halves2half2(__float2half_rn(f0 - __half2float(h0)),
                               __float2half_rn(f1 - __half2float(h1)));
            *(__half2*)(smc + 9216 + (r0 + 8) * 144 + col * 2) =
                __halves2half2(__float2half_rn(f2 - __half2float(h2)),
                               __float2half_rn(f3 - __half2float(h3)));
        }
    }

    uint32_t zb_h = sb, zb_l = sb + 9216;
    const float4* h4g = (const float4*)g_h;
    int NC = N * CC;

    for (int l = 0; l < 3; l++) {
        __syncthreads();
        {   const uint4* sh4 = (const uint4*)g_wr2t + (size_t)l * 1152;
            const uint4* sl4 = (const uint4*)g_wr2t + 3456 + (size_t)l * 1152;
            uint4* dh = (uint4*)(smc + 18432);
            uint4* dl = (uint4*)(smc + 36864);
            for (int i = tid; i < 1152; i += 256) { dh[i] = sh4[i]; dl[i] = sl4[i]; }
        }
        __syncthreads();

        uint32_t wb_h = sb + 18432, wb_l = sb + 36864;
        float C[8][4];
#pragma unroll
        for (int i = 0; i < 8; i++)
#pragma unroll
            for (int j = 0; j < 4; j++) C[i][j] = 0.f;

        for (int kb = 0; kb < 64; kb += 16) {
            uint32_t ah0, ah1, ah2, ah3, al0, al1, al2, al3;
            ldmx4(ah0, ah1, ah2, ah3, afa(zb_h, lane, mrow, kb, 72));
            ldmx4(al0, al1, al2, al3, afa(zb_l, lane, mrow, kb, 72));
#pragma unroll
            for (int nt2 = 0; nt2 < 4; nt2++) {
                uint32_t bh0, bh1, bh2, bh3, bl0, bl1, bl2, bl3;
                int nb = cw * 64 + nt2 * 16;
                ldmx4(bh0, bh1, bh2, bh3, bfa(wb_h, lane, nb, kb, 72));
                ldmx4(bl0, bl1, bl2, bl3, bfa(wb_l, lane, nb, kb, 72));
                mma_pair(C[2*nt2], C[2*nt2+1], ah0,ah1,ah2,ah3, al0,al1,al2,al3,
                         bh0,bh1,bh2,bh3, bl0,bl1,bl2,bl3);
            }
        }
        __syncthreads();

        {   int r0 = mrow + (lane >> 2);
            int c0 = cw * 64 + (lane & 3) * 2;
#pragma unroll
            for (int nt = 0; nt < 8; nt++) {
                int col = c0 + nt * 8;
                *(float2*)(stage + r0 * 132 + col) = make_float2(C[nt][0], C[nt][1]);
                *(float2*)(stage + (r0 + 8) * 132 + col) = make_float2(C[nt][2], C[nt][3]);
            }
        }
        __syncthreads();

        {   int base = wid * 8;
            int cnt = E - e0 - base; if (cnt > 8) cnt = 8;
            if (cnt > 0) {
                int nc = (l == 0) ? 1 : ((l == 1) ? 3 : 5);
                int co = (l == 0) ? 0 : ((l == 1) ? 1 : 4);
                float4 acc[5];
#pragma unroll
                for (int m = 0; m < 5; m++) acc[m] = make_float4(0.f, 0.f, 0.f, 0.f);
                int cur = rcv_s[base];
                float4 hv = h4g[(size_t)snd_s[base] * 32 + lane];
                float4 rv = *(const float4*)(stage + base * 132 + lane * 4);
                for (int j = 0; j < cnt; j++) {
                    int el = base + j;
                    float4 hv_n = hv, rv_n = rv;
                    if (j + 1 < cnt) {
                        hv_n = h4g[(size_t)snd_s[el + 1] * 32 + lane];
                        rv_n = *(const float4*)(stage + (el + 1) * 132 + lane * 4);
                    }
                    int rcv = rcv_s[el];
                    if (rcv != cur) {
                        float* bp = g_agg + (size_t)co * NC + (size_t)cur * CC + lane * 4;
                        for (int m = 0; m < nc; m++) {
                            red4(bp, acc[m]);
                            bp += NC;
                            acc[m] = make_float4(0.f, 0.f, 0.f, 0.f);
                        }
                        cur = rcv;
                    }
                    float cx = hv.x * rv.x, cy = hv.y * rv.y;
                    float cz = hv.z * rv.z, cw4 = hv.w * rv.w;
#pragma unroll
                    for (int m = 0; m < 5; m++) {
                        if (m >= nc) break;
                        float y = (l == 0) ? 1.f
                                : (l == 1) ? Ys[el * 8 + m]
                                           : Ys[el * 8 + 3 + m];
                        acc[m].x += cx * y; acc[m].y += cy * y;
                        acc[m].z += cz * y; acc[m].w += cw4 * y;
                    }
                    hv = hv_n; rv = rv_n;
                }
                float* bp = g_agg + (size_t)co * NC + (size_t)cur * CC + lane * 4;
                for (int m = 0; m < nc; m++) { red4(bp, acc[m]); bp += NC; }
            }
        }
    }
}

// ---------------- launch 7: fused readout (R12 version) --------------------------
__global__ void __launch_bounds__(256, 3)
readout_k(const float* __restrict__ W3, const float* __restrict__ b1,
          float* __restrict__ out, int N)
{
    extern __shared__ char smc[];
    uint32_t sb = s2u(smc);
    __half* Ah = (__half*)smc;
    __half* Al = (__half*)(smc + 17408);
    float* zf   = (float*)(smc + 55296);
    float* W3sm = (float*)(smc + 71680);
    float* b1sm = (float*)(smc + 71936);
    int tid = threadIdx.x, wid = tid >> 5, lane = tid & 31;
    int bm = blockIdx.x * 64;
    int rw = wid & 3, cw = wid >> 2;
    int mrow = rw * 16;

    if (tid < 64) { W3sm[tid] = W3[tid]; b1sm[tid] = b1[tid]; }
    {   const uint4* s = (const uint4*)g_w1t;
        uint4* d = (uint4*)(smc + 34816);
        for (int i = tid; i < 2176; i += 256) d[i] = s[i];
    }
    {   int r = tid >> 2, q4 = tid & 3;
        bool valid = (bm + r) < N;
        const float* Arow = g_hout + (size_t)(bm + r) * 128;
#pragma unroll
        for (int q = 0; q < 8; q++) {
            float4 v = valid ? ((const float4*)Arow)[q4 * 8 + q]
                             : make_float4(0.f, 0.f, 0.f, 0.f);
            cvt4(Ah, Al, r * 136 + q4 * 32 + q * 4, v);
        }
    }
    __syncthreads();

    float Cz[4][4];
#pragma unroll
    for (int i = 0; i < 4; i++)
#pragma unroll
        for (int j = 0; j < 4; j++) Cz[i][j] = 0.f;
    {
        uint32_t ab_h = sb, ab_l = sb + 17408, bb_h = sb + 34816, bb_l = sb + 52224;
        for (int kb = 0; kb < 128; kb += 16) {
            uint32_t ah0, ah1, ah2, ah3, al0, al1, al2, al3;
            ldmx4(ah0, ah1, ah2, ah3, afa(ab_h, lane, mrow, kb, 136));
            ldmx4(al0, al1, al2, al3, afa(ab_l, lane, mrow, kb, 136));
#pragma unroll
            for (int nt2 = 0; nt2 < 2; nt2++) {
                uint32_t bh0, bh1, bh2, bh3, bl0, bl1, bl2, bl3;
                int nb = cw * 32 + nt2 * 16;
                ldmx4(bh0, bh1, bh2, bh3, bfa(bb_h, lane, nb, kb, 136));
                ldmx4(bl0, bl1, bl2, bl3, bfa(bb_l, lane, nb, kb, 136));
                mma_pair(Cz[2*nt2], Cz[2*nt2+1], ah0,ah1,ah2,ah3, al0,al1,al2,al3,
                         bh0,bh1,bh2,bh3, bl0,bl1,bl2,bl3);
            }
        }
    }
    __syncthreads();

    {
        int r0 = mrow + (lane >> 2);
        int c0 = cw * 32 + (lane & 3) * 2;
#pragma unroll
        for (int nt = 0; nt < 4; nt++) {
            int col = c0 + nt * 8;
            float f0 = Cz[nt][0] + b1sm[col];
            float f1 = Cz[nt][1] + b1sm[col + 1];
            float f2 = Cz[nt][2] + b1sm[col];
            float f3 = Cz[nt][3] + b1sm[col + 1];
            f0 = f0 / (1.f + __expf(-f0));
            f1 = f1 / (1.f + __expf(-f1));
            f2 = f2 / (1.f + __expf(-f2));
            f3 = f3 / (1.f + __expf(-f3));
            __half h0 = __float2half_rn(f0), h1 = __float2half_rn(f1);
            __half h2 = __float2half_rn(f2), h3 = __float2half_rn(f3);
            *(__half2*)(smc + r0 * 144 + col * 2) = __halves2half2(h0, h1);
            *(__half2*)(smc + (r0 + 8) * 144 + col * 2) = __halves2half2(h2, h3);
            *(__half2*)(smc + 9216 + r0 * 144 + col * 2) =
                __halves2half2(__float2half_rn(f0 - __half2float(h0)),
                               __float2half_rn(f1 - __half2float(h1)));
            *(__half2*)(smc + 9216 + (r0 + 8) * 144 + col * 2) =
                __halves2half2(__float2half_rn(f2 - __half2float(h2)),
                               __float2half_rn(f3 - __half2float(h3)));
            zf[r0 * 64 + col] = f0; zf[r0 * 64 + col + 1] = f1;
            zf[(r0 + 8) * 64 + col] = f2; zf[(r0 + 8) * 64 + col + 1] = f3;
        }
    }
    __syncthreads();

    {   const uint4* s = (const uint4*)g_w2t;
        uint4* d = (uint4*)(smc + 18432);
        for (int i = tid; i < 2304; i += 256) d[i] = s[i];
    }
    __syncthreads();

    uint32_t zb_h = sb, zb_l = sb + 9216;
    uint32_t wb_h = sb + 18432, wb_l = sb + 36864;
    float C[8][4];
#pragma unroll
    for (int i = 0; i < 8; i++)
#pragma unroll
        for (int j = 0; j < 4; j++) C[i][j] = 0.f;

    for (int kb = 0; kb < 64; kb += 16) {
        uint32_t ah0, ah1, ah2, ah3, al0, al1, al2, al3;
        ldmx4(ah0, ah1, ah2, ah3, afa(zb_h, lane, mrow, kb, 72));
        ldmx4(al0, al1, al2, al3, afa(zb_l, lane, mrow, kb, 72));
#pragma unroll
        for (int nt2 = 0; nt2 < 4; nt2++) {
            uint32_t bh0, bh1, bh2, bh3, bl0, bl1, bl2, bl3;
            int nb = cw * 64 + nt2 * 16;
            ldmx4(bh0, bh1, bh2, bh3, bfa(wb_h, lane, nb, kb, 72));
            ldmx4(bl0, bl1, bl2, bl3, bfa(wb_l, lane, nb, kb, 72));
            mma_pair(C[2*nt2], C[2*nt2+1], ah0,ah1,ah2,ah3, al0,al1,al2,al3,
                     bh0,bh1,bh2,bh3, bl0,bl1,bl2,bl3);
        }
    }
    {   int r0 = bm + mrow + (lane >> 2);
        int c0 = cw * 64 + (lane & 3) * 2;
        bool v0 = r0 < N, v1 = (r0 + 8) < N;
#pragma unroll
        for (int nt = 0; nt < 8; nt++) {
            int col = c0 + nt * 8;
            if (v0) *(float2*)(out + (size_t)r0 * 128 + col) = make_float2(C[nt][0], C[nt][1]);
            if (v1) *(float2*)(out + (size_t)(r0 + 8) * 128 + col) = make_float2(C[nt][2], C[nt][3]);
        }
    }
    {   int nd = tid >> 2, t4 = tid & 3;
        float p = 0.f;
        if (bm + nd < N) {
#pragma unroll
            for (int d = 0; d < 16; d++)
                p = fmaf(zf[nd * 64 + t4 * 16 + d], W3sm[t4 * 16 + d], p);
        }
        p += __shfl_xor_sync(0xffffffffu, p, 1);
        p += __shfl_xor_sync(0xffffffffu, p, 2);
        if (t4 == 0 && bm + nd < N) g_zr[bm + nd] = p;
    }
}

// ---------------- symmetric contraction (now also clears agg) --------------------
__global__ void contract_k(const float* __restrict__ w0, const float* __restrict__ w1, int N)
{
    int i = blockIdx.x * blockDim.x + threadIdx.x;
    int NC = N * CC;
    if (i >= NC) return;
    int c = i & (CC - 1);
    const float* svt = g_svt;
    float* Bv = g_B;

    float s  = svt[i];
    float vx = svt[NC + i], vy = svt[2*NC + i], vz = svt[3*NC + i];
    float ta = svt[4*NC + i], tb = svt[5*NC + i], tcm = svt[6*NC + i];
    float td = svt[7*NC + i], te = svt[8*NC + i];

    // clear agg for next graph replay
#pragma unroll
    for (int k = 0; k < 9; k++) g_agg[(size_t)k * NC + i] = 0.f;

    float c3 = tcm * 0.5773502691896258f;
    float Txx = te - c3, Txy = ta, Txz = td;
    float Tyy = -te - c3, Tyz = tb;
    float Tzz = 2.f * c3;

    float v2 = vx*vx + vy*vy + vz*vz;
    float t2 = ta*ta + tb*tb + tcm*tcm + td*td + te*te;
    float Tvx = Txx*vx + Txy*vy + Txz*vz;
    float Tvy = Txy*vx + Tyy*vy + Tyz*vz;
    float Tvz = Txz*vx + Tyz*vy + Tzz*vz;
    float vTv = vx*Tvx + vy*Tvy + vz*Tvz;

    float B0 = w0[c]*s + w0[CC+c]*s*s + w0[2*CC+c]*v2 + w0[3*CC+c]*t2
             + w0[4*CC+c]*s*s*s + w0[5*CC+c]*s*v2 + w0[6*CC+c]*s*t2 + w0[7*CC+c]*vTv;

    float k0 = w1[c], k1 = w1[CC+c], k2 = w1[2*CC+c];
    float k3 = w1[3*CC+c], k4 = w1[4*CC+c], k5 = w1[5*CC+c];
    float f = k0 + k1*s + k3*s*s + k4*v2;
    float gT = k2 + k5*s;

    Bv[i] = B0;
    Bv[NC + i]   = f*vx + gT*Tvx;
    Bv[2*NC + i] = f*vy + gT*Tvy;
    Bv[3*NC + i] = f*vz + gT*Tvz;
}

// ---------------- finalize (gate precomputed; re-zeros histogram) -----------------
__global__ void final_k(const float* __restrict__ wv, float* __restrict__ out, int N)
{
    int gt = blockIdx.x * blockDim.x + threadIdx.x;
    if (gt <= NN) g_cnt[gt] = 0;
    int lane = threadIdx.x & 31;
    int node = gt >> 5;
    if (node >= N) return;
    int NC = N * CC;
    const float* h0 = g_hout;
    const float* h1 = g_hout + NC;

    float gate = g_zr[node];
    float sx = 0.f, sy = 0.f, sz = 0.f;
#pragma unroll
    for (int c = lane; c < CC; c += 32) {
        float w = wv[c];
        sx = fmaf(h1[node*CC + c], w, sx);
        sy = fmaf(h1[NC + node*CC + c], w, sy);
        sz = fmaf(h1[2*NC + node*CC + c], w, sz);
    }
#pragma unroll
    for (int off = 16; off; off >>= 1) {
        sx += __shfl_xor_sync(0xffffffffu, sx, off);
        sy += __shfl_xor_sync(0xffffffffu, sy, off);
        sz += __shfl_xor_sync(0xffffffffu, sz, off);
    }
    if (lane == 0) {
        float* ov = out + (size_t)N * 128 + (size_t)node * 3;
        ov[0] = sx * gate; ov[1] = sy * gate; ov[2] = sz * gate;
    }
    float* nf = out + (size_t)N * 131 + (size_t)node * 512;
#pragma unroll
    for (int c = lane; c < CC; c += 32) {
        nf[c] = h0[node*CC + c];
        nf[128 + 3*c + 0] = h1[node*CC + c];
        nf[128 + 3*c + 1] = h1[NC + node*CC + c];
        nf[128 + 3*c + 2] = h1[2*NC + node*CC + c];
    }
}

// ---------------- host launcher --------------------------------------------------
extern "C" void kernel_launch(void* const* d_in, const int* in_sizes, int n_in,
                              void* d_out, int out_size)
{
    const float* vectors    = (const float*)d_in[0];
    const float* lengths    = (const float*)d_in[1];
    const float* node_feats = (const float*)d_in[2];
    const float* edge_feats = (const float*)d_in[3];
    const int*   edge_index = (const int*)  d_in[4];
    const float* W_up = (const float*)d_in[5];
    const float* Wr1  = (const float*)d_in[6];
    const float* br1  = (const float*)d_in[7];
    const float* Wr2  = (const float*)d_in[8];
    const float* Wl0  = (const float*)d_in[9];
    const float* Wl1  = (const float*)d_in[10];
    const float* Wl2  = (const float*)d_in[11];
    const float* w0   = (const float*)d_in[12];
    const float* w1   = (const float*)d_in[13];
    const float* P0   = (const float*)d_in[14];
    const float* P1   = (const float*)d_in[15];
    const float* W1   = (const float*)d_in[16];
    const float* b1   = (const float*)d_in[17];
    const float* W2   = (const float*)d_in[18];
    const float* W3   = (const float*)d_in[19];
    const float* wv   = (const float*)d_in[20];
    float* out = (float*)d_out;

    int E = in_sizes[1];
    int N = in_sizes[2] / CC;
    int NC = N * CC;

    float *p_agg, *p_svt, *p_B, *p_hout;
    cudaGetSymbolAddress((void**)&p_agg,  g_agg);
    cudaGetSymbolAddress((void**)&p_svt,  g_svt);
    cudaGetSymbolAddress((void**)&p_B,    g_B);
    cudaGetSymbolAddress((void**)&p_hout, g_hout);

    int mt64 = (N + 63) / 64;
    const int SM_G = 69632;    // node_gemm v3: 3 CTA/SM
    const int SM_E = 72960;    // edge_fused: 3 CTA/SM
    const int SM_R = 72192;    // readout: 3 CTA/SM
    cudaFuncSetAttribute(mma128, cudaFuncAttributeMaxDynamicSharedMemorySize, SM_G);
    cudaFuncSetAttribute(permh, cudaFuncAttributeMaxDynamicSharedMemorySize, SM_G);
    cudaFuncSetAttribute(edge_fused, cudaFuncAttributeMaxDynamicSharedMemorySize, SM_E);
    cudaFuncSetAttribute(readout_k, cudaFuncAttributeMaxDynamicSharedMemorySize, SM_R);

    // 0: weight prep + rcv histogram
    prep_all<<<dim3(96, 11), 256>>>(W_up, Wl0, Wl1, Wl2, P0, P1, Wr1, Wr2,
                                    W1, W2, edge_index, E);
    // 1: exclusive scan
    scan_k<<<1, 1024>>>(N);
    // 2: perm scatter (y=0) + h GEMM n-halves (y=1,2)
    permh<<<dim3(160, 3), 256, SM_G>>>(edge_index, node_feats, E, N, mt64);
    // 3: fused edge kernel (ncu capture lands here)
    edge_fused<<<(E + 63) / 64, 256, SM_E>>>(vectors, edge_index, edge_feats, lengths,
                                             Wr1 + 128*64, br1, E, N);
    // 4: svt = agg @ Wl (9 comps x 2 n-halves)
    mma128<<<dim3(32, 18), 256, SM_G>>>(p_agg, p_svt, N, 1, mt64);
    // 5: contract + clear agg
    contract_k<<<(NC + 255) / 256, 256>>>(w0, w1, N);
    // 6: hout = B @ P (4 comps x 2 n-halves)
    mma128<<<dim3(74, 8), 256, SM_G>>>(p_B, p_hout, N, 2, mt64);
    // 7: fused readout (zr, scal->out, gate)
    readout_k<<<mt64, 256, SM_R>>>(W3, b1, out, N);
    // 8: finalize + zero histogram
    final_k<<<(N * 32 + 255) / 256, 256>>>(wv, out, N);
}

// round 15
// speedup vs baseline: 1.0277x; 1.0277x over previous
#include <cuda_runtime.h>
#include <cuda_fp16.h>
#include <math.h>
#include <stdint.h>

#define NN 10000
#define EE 160000
#define CC 128

// ---------------- scratch ------------------------------------------------------
__device__ float  g_h   [NN*CC];
__device__ float  g_agg [9*NN*CC];          // zero-init at load; re-cleared by svt pass
__device__ float  g_svt [9*NN*CC];
__device__ float  g_B   [4*NN*CC];
__device__ float  g_hout[4*NN*CC];
__device__ float  g_zr  [NN*64];            // gate per node (g_zr[node])
__device__ int    g_cnt [NN+1];             // zero-init; re-zeroed by final_k
__device__ int    g_perm[EE];
__device__ __half g_wt  [6*2*128*136];
__device__ __half g_wr1t[2*64*136];
__device__ __half g_wr2t[2*384*72];         // pre-scaled by 1/16
__device__ __half g_w1t [2*64*136];
__device__ __half g_w2t [2*128*72];

// ---------------- helpers -------------------------------------------------------
__device__ __forceinline__ uint32_t s2u(const void* p) {
    uint32_t a;
    asm("{ .reg .u64 t; cvta.to.shared.u64 t, %1; cvt.u32.u64 %0, t; }" : "=r"(a) : "l"(p));
    return a;
}
__device__ __forceinline__ void ldmx4(uint32_t& r0, uint32_t& r1, uint32_t& r2, uint32_t& r3,
                                      uint32_t a) {
    asm volatile("ldmatrix.sync.aligned.m8n8.x4.shared.b16 {%0,%1,%2,%3}, [%4];"
                 : "=r"(r0), "=r"(r1), "=r"(r2), "=r"(r3) : "r"(a));
}
__device__ __forceinline__ void mma4(float c[4], uint32_t a0, uint32_t a1, uint32_t a2,
                                     uint32_t a3, uint32_t b0, uint32_t b1) {
    asm volatile("mma.sync.aligned.m16n8k16.row.col.f32.f16.f16.f32 "
                 "{%0,%1,%2,%3},{%4,%5,%6,%7},{%8,%9},{%0,%1,%2,%3};"
                 : "+f"(c[0]), "+f"(c[1]), "+f"(c[2]), "+f"(c[3])
                 : "r"(a0), "r"(a1), "r"(a2), "r"(a3), "r"(b0), "r"(b1));
}
__device__ __forceinline__ uint32_t afa(uint32_t base, int lane, int mrow, int kb, int sh) {
    int row = mrow + (lane & 15);
    int k = kb + ((lane >> 4) << 3);
    return base + (uint32_t)(row * sh + k) * 2;
}
__device__ __forceinline__ uint32_t bfa(uint32_t base, int lane, int nb, int kb, int sh) {
    int n = nb + (lane & 7) + ((lane >> 4) << 3);
    int k = kb + (((lane >> 3) & 1) << 3);
    return base + (uint32_t)(n * sh + k) * 2;
}
__device__ __forceinline__ void red4(float* p, float4 v) {
    asm volatile("red.global.add.v4.f32 [%0], {%1,%2,%3,%4};"
                 :: "l"(p), "f"(v.x), "f"(v.y), "f"(v.z), "f"(v.w) : "memory");
}
__device__ __forceinline__ void mma_pair(float Ce[4], float Co[4],
    uint32_t ah0,uint32_t ah1,uint32_t ah2,uint32_t ah3,
    uint32_t al0,uint32_t al1,uint32_t al2,uint32_t al3,
    uint32_t bh0,uint32_t bh1,uint32_t bh2,uint32_t bh3,
    uint32_t bl0,uint32_t bl1,uint32_t bl2,uint32_t bl3)
{
    mma4(Ce, ah0, ah1, ah2, ah3, bh0, bh1);
    mma4(Co, ah0, ah1, ah2, ah3, bh2, bh3);
    mma4(Ce, al0, al1, al2, al3, bh0, bh1);
    mma4(Co, al0, al1, al2, al3, bh2, bh3);
    mma4(Ce, ah0, ah1, ah2, ah3, bl0, bl1);
    mma4(Co, ah0, ah1, ah2, ah3, bl2, bl3);
}
__device__ __forceinline__ void cvt4(__half* Hp, __half* Lp, int idx, float4 v) {
    __half h0 = __float2half_rn(v.x), h1 = __float2half_rn(v.y);
    __half h2 = __float2half_rn(v.z), h3 = __float2half_rn(v.w);
    ((__half2*)(Hp + idx))[0] = __halves2half2(h0, h1);
    ((__half2*)(Hp + idx))[1] = __halves2half2(h2, h3);
    ((__half2*)(Lp + idx))[0] = __halves2half2(__float2half_rn(v.x - __half2float(h0)),
                                               __float2half_rn(v.y - __half2float(h1)));
    ((__half2*)(Lp + idx))[1] = __halves2half2(__float2half_rn(v.z - __half2float(h2)),
                                               __float2half_rn(v.w - __half2float(h3)));
}

// ---------------- launch 0: weight prep + rcv histogram -------------------------
__global__ void prep_all(const float* W_up, const float* Wl0, const float* Wl1,
                         const float* Wl2, const float* P0, const float* P1,
                         const float* Wr1, const float* Wr2,
                         const float* W1, const float* W2,
                         const int* edge_index, int E)
{
    int w = blockIdx.y;
    if (w == 10) {
        for (int e = blockIdx.x * blockDim.x + threadIdx.x; e < E;
             e += gridDim.x * blockDim.x)
            atomicAdd(&g_cnt[edge_index[E + e]], 1);
        return;
    }
    const float* src; __half* dst; int K, Nr, ldw, stride; float sc = 1.f;
    const int TS = 2 * 128 * 136;
    switch (w) {
        case 0: src = W_up; dst = g_wt;        K=128; Nr=128; ldw=128; stride=136; break;
        case 1: src = Wl0;  dst = g_wt + 1*TS; K=128; Nr=128; ldw=128; stride=136; break;
        case 2: src = Wl1;  dst = g_wt + 2*TS; K=128; Nr=128; ldw=128; stride=136; break;
        case 3: src = Wl2;  dst = g_wt + 3*TS; K=128; Nr=128; ldw=128; stride=136; break;
        case 4: src = P0;   dst = g_wt + 4*TS; K=128; Nr=128; ldw=128; stride=136; break;
        case 5: src = P1;   dst = g_wt + 5*TS; K=128; Nr=128; ldw=128; stride=136; break;
        case 6: src = Wr1;  dst = g_wr1t;      K=128; Nr= 64; ldw= 64; stride=136; break;
        case 7: src = Wr2;  dst = g_wr2t;      K= 64; Nr=384; ldw=384; stride= 72;
                sc = 0.0625f; break;   // fold 1/AVG into Wr2
        case 8: src = W1;   dst = g_w1t;       K=128; Nr= 64; ldw= 64; stride=136; break;
        default:src = W2;   dst = g_w2t;       K= 64; Nr=128; ldw=128; stride= 72; break;
    }
    int i = blockIdx.x * blockDim.x + threadIdx.x;
    if (i >= K * Nr) return;
    int n = i / K, k = i % K;
    float v = src[(size_t)k * ldw + n] * sc;
    __half h = __float2half_rn(v);
    dst[(size_t)n * stride + k] = h;
    dst[(size_t)Nr * stride + (size_t)n * stride + k] = __float2half_rn(v - __half2float(h));
}

// ---------------- launch 1: exclusive scan of histogram -------------------------
__global__ void scan_k(int N)
{
    __shared__ int buf[1024];
    __shared__ int carry;
    int t = threadIdx.x;
    if (t == 0) carry = 0;
    __syncthreads();
    for (int base = 0; base < N; base += 1024) {
        int v = (base + t < N) ? g_cnt[base + t] : 0;
        buf[t] = v; __syncthreads();
#pragma unroll
        for (int off = 1; off < 1024; off <<= 1) {
            int x = (t >= off) ? buf[t - off] : 0;
            __syncthreads();
            buf[t] += x;
            __syncthreads();
        }
        int incl = buf[t];
        if (base + t < N) g_cnt[base + t] = carry + incl - v;
        __syncthreads();
        if (t == 1023) carry += incl;
        __syncthreads();
    }
}

// ---------------- node-GEMM: 64-row tiles, 2-D warp tiling, 104.4KB, 2 CTA/SM ----
__device__ __forceinline__ void node_gemm(float* A, float* O, int M, int tile,
                                          int tiles, char* smem, int clearA,
                                          int bx, int gx)
{
    __half* Ah = (__half*)smem;
    __half* Al = (__half*)(smem + 17408);
    uint32_t sb = s2u(smem);
    int tid = threadIdx.x, wid = tid >> 5, lane = tid & 31;
    int rw = wid & 3, cw = wid >> 2;
    int mrow = rw * 16;

    {   const uint4* s = (const uint4*)(g_wt + (size_t)tile * (2*128*136));
        uint4* d = (uint4*)(smem + 34816);
        for (int i = tid; i < 4352; i += 256) d[i] = s[i];
    }
    uint32_t ab_h = sb, ab_l = sb + 17408, bb_h = sb + 34816, bb_l = sb + 69632;
    int rr = tid >> 2, q4 = tid & 3;

    for (int tl = bx; tl < tiles; tl += gx) {
        int bm = tl * 64;
        bool valid = (bm + rr) < M;
        float* Arow = A + (size_t)(bm + rr) * 128;
        {
#pragma unroll
            for (int q = 0; q < 8; q++) {
                float4 v = valid ? ((const float4*)Arow)[q4 * 8 + q]
                                 : make_float4(0.f, 0.f, 0.f, 0.f);
                cvt4(Ah, Al, rr * 136 + q4 * 32 + q * 4, v);
            }
            if (clearA && valid) {
                float4 z = make_float4(0.f, 0.f, 0.f, 0.f);
#pragma unroll
                for (int q = 0; q < 8; q++) ((float4*)Arow)[q4 * 8 + q] = z;
            }
        }
        __syncthreads();

        float C[8][4];
#pragma unroll
        for (int i = 0; i < 8; i++)
#pragma unroll
            for (int j = 0; j < 4; j++) C[i][j] = 0.f;

        for (int kb = 0; kb < 128; kb += 16) {
            uint32_t ah0, ah1, ah2, ah3, al0, al1, al2, al3;
            ldmx4(ah0, ah1, ah2, ah3, afa(ab_h, lane, mrow, kb, 136));
            ldmx4(al0, al1, al2, al3, afa(ab_l, lane, mrow, kb, 136));
#pragma unroll
            for (int nt2 = 0; nt2 < 4; nt2++) {
                uint32_t bh0, bh1, bh2, bh3, bl0, bl1, bl2, bl3;
                int nb = cw * 64 + nt2 * 16;
                ldmx4(bh0, bh1, bh2, bh3, bfa(bb_h, lane, nb, kb, 136));
                ldmx4(bl0, bl1, bl2, bl3, bfa(bb_l, lane, nb, kb, 136));
                mma_pair(C[2*nt2], C[2*nt2+1], ah0,ah1,ah2,ah3, al0,al1,al2,al3,
                         bh0,bh1,bh2,bh3, bl0,bl1,bl2,bl3);
            }
        }

        int r0 = bm + mrow + (lane >> 2);
        int c0 = cw * 64 + (lane & 3) * 2;
        bool v0 = r0 < M, v1 = (r0 + 8) < M;
#pragma unroll
        for (int nt = 0; nt < 8; nt++) {
            int col = c0 + nt * 8;
            if (v0) *(float2*)(O + (size_t)r0 * 128 + col) = make_float2(C[nt][0], C[nt][1]);
            if (v1) *(float2*)(O + (size_t)(r0 + 8) * 128 + col) = make_float2(C[nt][2], C[nt][3]);
        }
        __syncthreads();
    }
}

// ---------------- launch 2: y0 = permutation scatter, y1 = h GEMM ---------------
__global__ void __launch_bounds__(256, 2)
permh(const int* __restrict__ edge_index, const float* __restrict__ node_feats,
      int E, int M, int mt)
{
    extern __shared__ char smem[];
    if (blockIdx.y == 0) {
        for (int e = blockIdx.x * blockDim.x + threadIdx.x; e < E;
             e += gridDim.x * blockDim.x) {
            int rcv = edge_index[E + e];
            int pos = atomicAdd(&g_cnt[rcv], 1);
            g_perm[pos] = e;
        }
        return;
    }
    node_gemm((float*)node_feats, g_h, M, 0, mt, smem, 0, blockIdx.x, gridDim.x);
}

// ---------------- launches 4/6: svt = agg@Wl (clears agg), hout = B@P -----------
__global__ void __launch_bounds__(256, 2)
mma128(float* __restrict__ A0, float* __restrict__ O0, int M, int phase, int mt)
{
    extern __shared__ char smem[];
    int comp = blockIdx.y;
    int tile = (phase == 1) ? ((comp == 0) ? 1 : (comp < 4 ? 2 : 3))
                            : ((comp == 0) ? 4 : 5);
    node_gemm(A0 + (size_t)comp * M * 128, O0 + (size_t)comp * M * 128,
              M, tile, mt, smem, phase == 1, blockIdx.x, gridDim.x);
}

// ---------------- launch 3: fused edge kernel, 64 edges, 72.96KB -> 3 CTA/SM -----
__global__ void __launch_bounds__(256, 3)
edge_fused(const float* __restrict__ vectors, const int* __restrict__ edge_index,
           const float* __restrict__ edge_feats, const float* __restrict__ lengths,
           const float* __restrict__ wlast, const float* __restrict__ bias,
           int E, int N)
{
    extern __shared__ char smc[];
    uint32_t sb = s2u(smc);
    __half* efAh = (__half*)smc;
    __half* efAl = (__half*)(smc + 17408);
    float* wl_sm = (float*)(smc + 69632);
    float* b_sm  = (float*)(smc + 69888);
    float* Ys    = (float*)(smc + 70144);
    int* snd_s   = (int*)(smc + 72192);
    int* rcv_s   = (int*)(smc + 72448);
    float* len_s = (float*)(smc + 72704);
    float* stage = (float*)(smc + 18432);
    int tid = threadIdx.x, wid = tid >> 5, lane = tid & 31;
    int e0 = blockIdx.x * 64;
    int rw = wid & 3, cw = wid >> 2;
    int mrow = rw * 16;

    if (tid < 64) { wl_sm[tid] = wlast[tid]; b_sm[tid] = bias[tid]; }
    {   const uint4* s = (const uint4*)g_wr1t;
        uint4* d = (uint4*)(smc + 34816);
        for (int i = tid; i < 2176; i += 256) d[i] = s[i];
    }
    {   int r = tid >> 2, q4 = tid & 3;
        bool valid = (e0 + r) < E;
        const float* Arow = edge_feats + (valid ? (size_t)g_perm[e0 + r] * 128 : 0);
#pragma unroll
        for (int q = 0; q < 8; q++) {
            float4 v = valid ? ((const float4*)Arow)[q4 * 8 + q]
                             : make_float4(0.f, 0.f, 0.f, 0.f);
            cvt4(efAh, efAl, r * 136 + q4 * 32 + q * 4, v);
        }
    }
    if (tid < 64) {
        int e = e0 + tid;
        int snd = 0, rcv = 0;
        float vx = 0.f, vy = 1.f, vz = 0.f, ln = 0.f;
        if (e < E) {
            int pe = g_perm[e];
            snd = edge_index[pe]; rcv = edge_index[E + pe];
            vx = vectors[3*pe]; vy = vectors[3*pe+1]; vz = vectors[3*pe+2];
            ln = lengths[pe];
        }
        snd_s[tid] = snd; rcv_s[tid] = rcv; len_s[tid] = ln;
        float inv = 1.f / (sqrtf(vx*vx + vy*vy + vz*vz) + 1e-9f);
        float ux = vx*inv, uy = vy*inv, uz = vz*inv;
        const float S3 = 1.7320508075688772f, S15 = 3.8729833462074170f;
        const float S15H = 1.9364916731037085f, S5H = 1.1180339887498949f;
        float* y = Ys + tid * 8;
        y[0] = S3*ux; y[1] = S3*uy; y[2] = S3*uz;
        y[3] = S15*ux*uy; y[4] = S15*uy*uz; y[5] = S5H*(3.f*uz*uz - 1.f);
        y[6] = S15*ux*uz; y[7] = S15H*(ux*ux - uy*uy);
    }
    __syncthreads();

    // radial MMA: z = ef @ Wr1
    float Cz[4][4];
#pragma unroll
    for (int i = 0; i < 4; i++)
#pragma unroll
        for (int j = 0; j < 4; j++) Cz[i][j] = 0.f;
    {
        uint32_t ab_h = sb, ab_l = sb + 17408, bb_h = sb + 34816, bb_l = sb + 52224;
        for (int kb = 0; kb < 128; kb += 16) {
            uint32_t ah0, ah1, ah2, ah3, al0, al1, al2, al3;
            ldmx4(ah0, ah1, ah2, ah3, afa(ab_h, lane, mrow, kb, 136));
            ldmx4(al0, al1, al2, al3, afa(ab_l, lane, mrow, kb, 136));
#pragma unroll
            for (int nt2 = 0; nt2 < 2; nt2++) {
                uint32_t bh0, bh1, bh2, bh3, bl0, bl1, bl2, bl3;
                int nb = cw * 32 + nt2 * 16;
                ldmx4(bh0, bh1, bh2, bh3, bfa(bb_h, lane, nb, kb, 136));
                ldmx4(bl0, bl1, bl2, bl3, bfa(bb_l, lane, nb, kb, 136));
                mma_pair(Cz[2*nt2], Cz[2*nt2+1], ah0,ah1,ah2,ah3, al0,al1,al2,al3,
                         bh0,bh1,bh2,bh3, bl0,bl1,bl2,bl3);
            }
        }
    }
    __syncthreads();

    // epilogue: silu -> z hi/lo smem (stride 72)
    {
        int r0 = mrow + (lane >> 2);
        int c0 = cw * 32 + (lane & 3) * 2;
        float len0 = len_s[r0];
        float len1 = len_s[r0 + 8];
#pragma unroll
        for (int nt = 0; nt < 4; nt++) {
            int col = c0 + nt * 8;
            float wl0 = wl_sm[col], wl1 = wl_sm[col + 1];
            float bb0 = b_sm[col],  bb1 = b_sm[col + 1];
            float f0 = Cz[nt][0] + len0 * wl0 + bb0;
            float f1 = Cz[nt][1] + len0 * wl1 + bb1;
            float f2 = Cz[nt][2] + len1 * wl0 + bb0;
            float f3 = Cz[nt][3] + len1 * wl1 + bb1;
            f0 = f0 / (1.f + __expf(-f0));
            f1 = f1 / (1.f + __expf(-f1));
            f2 = f2 / (1.f + __expf(-f2));
            f3 = f3 / (1.f + __expf(-f3));
            __half h0 = __float2half_rn(f0), h1 = __float2half_rn(f1);
            __half h2 = __float2half_rn(f2), h3 = __float2half_rn(f3);
            *(__half2*)(smc + r0 * 144 + col * 2) = __halves2half2(h0, h1);
            *(__half2*)(smc + (r0 + 8) * 144 + col * 2) = __halves2half2(h2, h3);
            *(__half2*)(smc + 9216 + r0 * 144 + col * 2) =
                __halves2half2(__float2half_rn(f0 - __half2float(h0)),
                               __float2half_rn(f1 - __half2float(h1)));
            *(__half2*)(smc + 9216 + (r0 + 8) * 144 + col * 2) =
                __halves2half2(__float2half_rn(f2 - __half2float(h2)),
                               __float2half_rn(f3 - __half2float(h3)));
        }
    }

    uint32_t zb_h = sb, zb_l = sb + 9216;
    const float4* h4g = (const float4*)g_h;
    int NC = N * CC;

    for (int l = 0; l < 3; l++) {
        __syncthreads();
        {   const uint4* sh4 = (const uint4*)g_wr2t + (size_t)l * 1152;
            const uint4* sl4 = (const uint4*)g_wr2t + 3456 + (size_t)l * 1152;
            uint4* dh = (uint4*)(smc + 18432);
            uint4* dl = (uint4*)(smc + 36864);
            for (int i = tid; i < 1152; i += 256) { dh[i] = sh4[i]; dl[i] = sl4[i]; }
        }
        __syncthreads();

        uint32_t wb_h = sb + 18432, wb_l = sb + 36864;
        float C[8][4];
#pragma unroll
        for (int i = 0; i < 8; i++)
#pragma unroll
            for (int j = 0; j < 4; j++) C[i][j] = 0.f;

        for (int kb = 0; kb < 64; kb += 16) {
            uint32_t ah0, ah1, ah2, ah3, al0, al1, al2, al3;
            ldmx4(ah0, ah1, ah2, ah3, afa(zb_h, lane, mrow, kb, 72));
            ldmx4(al0, al1, al2, al3, afa(zb_l, lane, mrow, kb, 72));
#pragma unroll
            for (int nt2 = 0; nt2 < 4; nt2++) {
                uint32_t bh0, bh1, bh2, bh3, bl0, bl1, bl2, bl3;
                int nb = cw * 64 + nt2 * 16;
                ldmx4(bh0, bh1, bh2, bh3, bfa(wb_h, lane, nb, kb, 72));
                ldmx4(bl0, bl1, bl2, bl3, bfa(wb_l, lane, nb, kb, 72));
                mma_pair(C[2*nt2], C[2*nt2+1], ah0,ah1,ah2,ah3, al0,al1,al2,al3,
                         bh0,bh1,bh2,bh3, bl0,bl1,bl2,bl3);
            }
        }
        __syncthreads();

        {   int r0 = mrow + (lane >> 2);
            int c0 = cw * 64 + (lane & 3) * 2;
#pragma unroll
            for (int nt = 0; nt < 8; nt++) {
                int col = c0 + nt * 8;
                *(float2*)(stage + r0 * 132 + col) = make_float2(C[nt][0], C[nt][1]);
                *(float2*)(stage + (r0 + 8) * 132 + col) = make_float2(C[nt][2], C[nt][3]);
            }
        }
        __syncthreads();

        {   // run-merged scatter, warp owns 8 edges, red4
            int base = wid * 8;
            int cnt = E - e0 - base; if (cnt > 8) cnt = 8;
            if (cnt > 0) {
                int nc = (l == 0) ? 1 : ((l == 1) ? 3 : 5);
                int co = (l == 0) ? 0 : ((l == 1) ? 1 : 4);
                float4 acc[5];
#pragma unroll
                for (int m = 0; m < 5; m++) acc[m] = make_float4(0.f, 0.f, 0.f, 0.f);
                int cur = rcv_s[base];
                float4 hv = h4g[(size_t)snd_s[base] * 32 + lane];
                float4 rv = *(const float4*)(stage + base * 132 + lane * 4);
                for (int j = 0; j < cnt; j++) {
                    int el = base + j;
                    float4 hv_n = hv, rv_n = rv;
                    if (j + 1 < cnt) {
                        hv_n = h4g[(size_t)snd_s[el + 1] * 32 + lane];
                        rv_n = *(const float4*)(stage + (el + 1) * 132 + lane * 4);
                    }
                    int rcv = rcv_s[el];
                    if (rcv != cur) {
                        float* bp = g_agg + (size_t)co * NC + (size_t)cur * CC + lane * 4;
                        for (int m = 0; m < nc; m++) {
                            red4(bp, acc[m]);
                            bp += NC;
                            acc[m] = make_float4(0.f, 0.f, 0.f, 0.f);
                        }
                        cur = rcv;
                    }
                    float cx = hv.x * rv.x, cy = hv.y * rv.y;
                    float cz = hv.z * rv.z, cw4 = hv.w * rv.w;
#pragma unroll
                    for (int m = 0; m < 5; m++) {
                        if (m >= nc) break;
                        float y = (l == 0) ? 1.f
                                : (l == 1) ? Ys[el * 8 + m]
                                           : Ys[el * 8 + 3 + m];
                        acc[m].x += cx * y; acc[m].y += cy * y;
                        acc[m].z += cz * y; acc[m].w += cw4 * y;
                    }
                    hv = hv_n; rv = rv_n;
                }
                float* bp = g_agg + (size_t)co * NC + (size_t)cur * CC + lane * 4;
                for (int m = 0; m < nc; m++) { red4(bp, acc[m]); bp += NC; }
            }
        }
    }
}

// ---------------- launch 7: fused readout ----------------------------------------
__global__ void __launch_bounds__(256, 3)
readout_k(const float* __restrict__ W3, const float* __restrict__ b1,
          float* __restrict__ out, int N)
{
    extern __shared__ char smc[];
    uint32_t sb = s2u(smc);
    __half* Ah = (__half*)smc;
    __half* Al = (__half*)(smc + 17408);
    float* zf   = (float*)(smc + 55296);
    float* W3sm = (float*)(smc + 71680);
    float* b1sm = (float*)(smc + 71936);
    int tid = threadIdx.x, wid = tid >> 5, lane = tid & 31;
    int bm = blockIdx.x * 64;
    int rw = wid & 3, cw = wid >> 2;
    int mrow = rw * 16;

    if (tid < 64) { W3sm[tid] = W3[tid]; b1sm[tid] = b1[tid]; }
    {   const uint4* s = (const uint4*)g_w1t;
        uint4* d = (uint4*)(smc + 34816);
        for (int i = tid; i < 2176; i += 256) d[i] = s[i];
    }
    {   int r = tid >> 2, q4 = tid & 3;
        bool valid = (bm + r) < N;
        const float* Arow = g_hout + (size_t)(bm + r) * 128;
#pragma unroll
        for (int q = 0; q < 8; q++) {
            float4 v = valid ? ((const float4*)Arow)[q4 * 8 + q]
                             : make_float4(0.f, 0.f, 0.f, 0.f);
            cvt4(Ah, Al, r * 136 + q4 * 32 + q * 4, v);
        }
    }
    __syncthreads();

    float Cz[4][4];
#pragma unroll
    for (int i = 0; i < 4; i++)
#pragma unroll
        for (int j = 0; j < 4; j++) Cz[i][j] = 0.f;
    {
        uint32_t ab_h = sb, ab_l = sb + 17408, bb_h = sb + 34816, bb_l = sb + 52224;
        for (int kb = 0; kb < 128; kb += 16) {
            uint32_t ah0, ah1, ah2, ah3, al0, al1, al2, al3;
            ldmx4(ah0, ah1, ah2, ah3, afa(ab_h, lane, mrow, kb, 136));
            ldmx4(al0, al1, al2, al3, afa(ab_l, lane, mrow, kb, 136));
#pragma unroll
            for (int nt2 = 0; nt2 < 2; nt2++) {
                uint32_t bh0, bh1, bh2, bh3, bl0, bl1, bl2, bl3;
                int nb = cw * 32 + nt2 * 16;
                ldmx4(bh0, bh1, bh2, bh3, bfa(bb_h, lane, nb, kb, 136));
                ldmx4(bl0, bl1, bl2, bl3, bfa(bb_l, lane, nb, kb, 136));
                mma_pair(Cz[2*nt2], Cz[2*nt2+1], ah0,ah1,ah2,ah3, al0,al1,al2,al3,
                         bh0,bh1,bh2,bh3, bl0,bl1,bl2,bl3);
            }
        }
    }
    __syncthreads();

    {
        int r0 = mrow + (lane >> 2);
        int c0 = cw * 32 + (lane & 3) * 2;
#pragma unroll
        for (int nt = 0; nt < 4; nt++) {
            int col = c0 + nt * 8;
            float f0 = Cz[nt][0] + b1sm[col];
            float f1 = Cz[nt][1] + b1sm[col + 1];
            float f2 = Cz[nt][2] + b1sm[col];
            float f3 = Cz[nt][3] + b1sm[col + 1];
            f0 = f0 / (1.f + __expf(-f0));
            f1 = f1 / (1.f + __expf(-f1));
            f2 = f2 / (1.f + __expf(-f2));
            f3 = f3 / (1.f + __expf(-f3));
            __half h0 = __float2half_rn(f0), h1 = __float2half_rn(f1);
            __half h2 = __float2half_rn(f2), h3 = __float2half_rn(f3);
            *(__half2*)(smc + r0 * 144 + col * 2) = __halves2half2(h0, h1);
            *(__half2*)(smc + (r0 + 8) * 144 + col * 2) = __halves2half2(h2, h3);
            *(__half2*)(smc + 9216 + r0 * 144 + col * 2) =
                __halves2half2(__float2half_rn(f0 - __half2float(h0)),
                               __float2half_rn(f1 - __half2float(h1)));
            *(__half2*)(smc + 9216 + (r0 + 8) * 144 + col * 2) =
                __halves2half2(__float2half_rn(f2 - __half2float(h2)),
                               __float2half_rn(f3 - __half2float(h3)));
            zf[r0 * 64 + col] = f0; zf[r0 * 64 + col + 1] = f1;
            zf[(r0 + 8) * 64 + col] = f2; zf[(r0 + 8) * 64 + col + 1] = f3;
        }
    }
    __syncthreads();

    {   const uint4* s = (const uint4*)g_w2t;
        uint4* d = (uint4*)(smc + 18432);
        for (int i = tid; i < 2304; i += 256) d[i] = s[i];
    }
    __syncthreads();

    uint32_t zb_h = sb, zb_l = sb + 9216;
    uint32_t wb_h = sb + 18432, wb_l = sb + 36864;
    float C[8][4];
#pragma unroll
    for (int i = 0; i < 8; i++)
#pragma unroll
        for (int j = 0; j < 4; j++) C[i][j] = 0.f;

    for (int kb = 0; kb < 64; kb += 16) {
        uint32_t ah0, ah1, ah2, ah3, al0, al1, al2, al3;
        ldmx4(ah0, ah1, ah2, ah3, afa(zb_h, lane, mrow, kb, 72));
        ldmx4(al0, al1, al2, al3, afa(zb_l, lane, mrow, kb, 72));
#pragma unroll
        for (int nt2 = 0; nt2 < 4; nt2++) {
            uint32_t bh0, bh1, bh2, bh3, bl0, bl1, bl2, bl3;
            int nb = cw * 64 + nt2 * 16;
            ldmx4(bh0, bh1, bh2, bh3, bfa(wb_h, lane, nb, kb, 72));
            ldmx4(bl0, bl1, bl2, bl3, bfa(wb_l, lane, nb, kb, 72));
            mma_pair(C[2*nt2], C[2*nt2+1], ah0,ah1,ah2,ah3, al0,al1,al2,al3,
                     bh0,bh1,bh2,bh3, bl0,bl1,bl2,bl3);
        }
    }
    {   int r0 = bm + mrow + (lane >> 2);
        int c0 = cw * 64 + (lane & 3) * 2;
        bool v0 = r0 < N, v1 = (r0 + 8) < N;
#pragma unroll
        for (int nt = 0; nt < 8; nt++) {
            int col = c0 + nt * 8;
            if (v0) *(float2*)(out + (size_t)r0 * 128 + col) = make_float2(C[nt][0], C[nt][1]);
            if (v1) *(float2*)(out + (size_t)(r0 + 8) * 128 + col) = make_float2(C[nt][2], C[nt][3]);
        }
    }
    {   int nd = tid >> 2, t4 = tid & 3;
        float p = 0.f;
        if (bm + nd < N) {
#pragma unroll
            for (int d = 0; d < 16; d++)
                p = fmaf(zf[nd * 64 + t4 * 16 + d], W3sm[t4 * 16 + d], p);
        }
        p += __shfl_xor_sync(0xffffffffu, p, 1);
        p += __shfl_xor_sync(0xffffffffu, p, 2);
        if (t4 == 0 && bm + nd < N) g_zr[bm + nd] = p;
    }
}

// ---------------- symmetric contraction ----------------------------------------
__global__ void contract_k(const float* __restrict__ w0, const float* __restrict__ w1, int N)
{
    int i = blockIdx.x * blockDim.x + threadIdx.x;
    int NC = N * CC;
    if (i >= NC) return;
    int c = i & (CC - 1);
    const float* svt = g_svt;
    float* Bv = g_B;

    float s  = svt[i];
    float vx = svt[NC + i], vy = svt[2*NC + i], vz = svt[3*NC + i];
    float ta = svt[4*NC + i], tb = svt[5*NC + i], tcm = svt[6*NC + i];
    float td = svt[7*NC + i], te = svt[8*NC + i];

    float c3 = tcm * 0.5773502691896258f;
    float Txx = te - c3, Txy = ta, Txz = td;
    float Tyy = -te - c3, Tyz = tb;
    float Tzz = 2.f * c3;

    float v2 = vx*vx + vy*vy + vz*vz;
    float t2 = ta*ta + tb*tb + tcm*tcm + td*td + te*te;
    float Tvx = Txx*vx + Txy*vy + Txz*vz;
    float Tvy = Txy*vx + Tyy*vy + Tyz*vz;
    float Tvz = Txz*vx + Tyz*vy + Tzz*vz;
    float vTv = vx*Tvx + vy*Tvy + vz*Tvz;

    float B0 = w0[c]*s + w0[CC+c]*s*s + w0[2*CC+c]*v2 + w0[3*CC+c]*t2
             + w0[4*CC+c]*s*s*s + w0[5*CC+c]*s*v2 + w0[6*CC+c]*s*t2 + w0[7*CC+c]*vTv;

    float k0 = w1[c], k1 = w1[CC+c], k2 = w1[2*CC+c];
    float k3 = w1[3*CC+c], k4 = w1[4*CC+c], k5 = w1[5*CC+c];
    float f = k0 + k1*s + k3*s*s + k4*v2;
    float gT = k2 + k5*s;

    Bv[i] = B0;
    Bv[NC + i]   = f*vx + gT*Tvx;
    Bv[2*NC + i] = f*vy + gT*Tvy;
    Bv[3*NC + i] = f*vz + gT*Tvz;
}

// ---------------- finalize (gate precomputed; also re-zeros histogram) -----------
__global__ void final_k(const float* __restrict__ wv, float* __restrict__ out, int N)
{
    int gt = blockIdx.x * blockDim.x + threadIdx.x;
    if (gt <= NN) g_cnt[gt] = 0;
    int lane = threadIdx.x & 31;
    int node = gt >> 5;
    if (node >= N) return;
    int NC = N * CC;
    const float* h0 = g_hout;
    const float* h1 = g_hout + NC;

    float gate = g_zr[node];
    float sx = 0.f, sy = 0.f, sz = 0.f;
#pragma unroll
    for (int c = lane; c < CC; c += 32) {
        float w = wv[c];
        sx = fmaf(h1[node*CC + c], w, sx);
        sy = fmaf(h1[NC + node*CC + c], w, sy);
        sz = fmaf(h1[2*NC + node*CC + c], w, sz);
    }
#pragma unroll
    for (int off = 16; off; off >>= 1) {
        sx += __shfl_xor_sync(0xffffffffu, sx, off);
        sy += __shfl_xor_sync(0xffffffffu, sy, off);
        sz += __shfl_xor_sync(0xffffffffu, sz, off);
    }
    if (lane == 0) {
        float* ov = out + (size_t)N * 128 + (size_t)node * 3;
        ov[0] = sx * gate; ov[1] = sy * gate; ov[2] = sz * gate;
    }
    float* nf = out + (size_t)N * 131 + (size_t)node * 512;
#pragma unroll
    for (int c = lane; c < CC; c += 32) {
        nf[c] = h0[node*CC + c];
        nf[128 + 3*c + 0] = h1[node*CC + c];
        nf[128 + 3*c + 1] = h1[NC + node*CC + c];
        nf[128 + 3*c + 2] = h1[2*NC + node*CC + c];
    }
}

// ---------------- host launcher --------------------------------------------------
extern "C" void kernel_launch(void* const* d_in, const int* in_sizes, int n_in,
                              void* d_out, int out_size)
{
    const float* vectors    = (const float*)d_in[0];
    const float* lengths    = (const float*)d_in[1];
    const float* node_feats = (const float*)d_in[2];
    const float* edge_feats = (const float*)d_in[3];
    const int*   edge_index = (const int*)  d_in[4];
    const float* W_up = (const float*)d_in[5];
    const float* Wr1  = (const float*)d_in[6];
    const float* br1  = (const float*)d_in[7];
    const float* Wr2  = (const float*)d_in[8];
    const float* Wl0  = (const float*)d_in[9];
    const float* Wl1  = (const float*)d_in[10];
    const float* Wl2  = (const float*)d_in[11];
    const float* w0   = (const float*)d_in[12];
    const float* w1   = (const float*)d_in[13];
    const float* P0   = (const float*)d_in[14];
    const float* P1   = (const float*)d_in[15];
    const float* W1   = (const float*)d_in[16];
    const float* b1   = (const float*)d_in[17];
    const float* W2   = (const float*)d_in[18];
    const float* W3   = (const float*)d_in[19];
    const float* wv   = (const float*)d_in[20];
    float* out = (float*)d_out;

    int E = in_sizes[1];
    int N = in_sizes[2] / CC;
    int NC = N * CC;

    float *p_agg, *p_svt, *p_B, *p_hout;
    cudaGetSymbolAddress((void**)&p_agg,  g_agg);
    cudaGetSymbolAddress((void**)&p_svt,  g_svt);
    cudaGetSymbolAddress((void**)&p_B,    g_B);
    cudaGetSymbolAddress((void**)&p_hout, g_hout);

    int mt64 = (N + 63) / 64;
    const int SM_G = 104448;   // node_gemm: 2 CTA/SM
    const int SM_E = 72960;    // edge_fused: 3 CTA/SM
    const int SM_R = 72192;    // readout: 3 CTA/SM
    cudaFuncSetAttribute(mma128, cudaFuncAttributeMaxDynamicSharedMemorySize, SM_G);
    cudaFuncSetAttribute(permh, cudaFuncAttributeMaxDynamicSharedMemorySize, SM_G);
    cudaFuncSetAttribute(edge_fused, cudaFuncAttributeMaxDynamicSharedMemorySize, SM_E);
    cudaFuncSetAttribute(readout_k, cudaFuncAttributeMaxDynamicSharedMemorySize, SM_R);

    // 0: weight prep + rcv histogram
    prep_all<<<dim3(96, 11), 256>>>(W_up, Wl0, Wl1, Wl2, P0, P1, Wr1, Wr2,
                                    W1, W2, edge_index, E);
    // 1: exclusive scan
    scan_k<<<1, 1024>>>(N);
    // 2: perm scatter (y=0) + h = nf@W_up (y=1)
    permh<<<dim3(160, 2), 256, SM_G>>>(edge_index, node_feats, E, N, mt64);
    // 3: fused edge kernel (ncu capture lands here)
    edge_fused<<<(E + 63) / 64, 256, SM_E>>>(vectors, edge_index, edge_feats, lengths,
                                             Wr1 + 128*64, br1, E, N);
    // 4: svt = agg @ Wl (clears agg for next run)
    mma128<<<dim3(32, 9), 256, SM_G>>>(p_agg, p_svt, N, 1, mt64);
    // 5
    contract_k<<<(NC + 255) / 256, 256>>>(w0, w1, N);
    // 6: hout = B @ P
    mma128<<<dim3(74, 4), 256, SM_G>>>(p_B, p_hout, N, 2, mt64);
    // 7: fused readout (zr, scal->out, gate)
    readout_k<<<mt64, 256, SM_R>>>(W3, b1, out, N);
    // 8: finalize + zero histogram
    final_k<<<(N * 32 + 255) / 256, 256>>>(wv, out, N);
}

// round 16
// speedup vs baseline: 1.0475x; 1.0193x over previous
#include <cuda_runtime.h>
#include <cuda_fp16.h>
#include <math.h>
#include <stdint.h>

#define NN 10000
#define EE 160000
#define CC 128

// ---------------- scratch ------------------------------------------------------
__device__ float  g_h   [NN*CC];
__device__ float  g_agg [9*NN*CC];          // zero-init at load; re-cleared by svt pass
__device__ float  g_svt [9*NN*CC];
__device__ float  g_B   [4*NN*CC];
__device__ float  g_hout[4*NN*CC];
__device__ float  g_zr  [NN*64];            // gate per node (g_zr[node])
__device__ int    g_cnt [NN+1];             // zero-init; re-zeroed by final_k
__device__ int    g_perm[EE];
__device__ __half g_wt  [6*2*128*136];
__device__ __half g_wr1t[2*64*136];
__device__ __half g_wr2t[2*384*72];         // pre-scaled by 1/16
__device__ __half g_w1t [2*64*136];
__device__ __half g_w2t [2*128*72];

// ---------------- helpers -------------------------------------------------------
__device__ __forceinline__ uint32_t s2u(const void* p) {
    uint32_t a;
    asm("{ .reg .u64 t; cvta.to.shared.u64 t, %1; cvt.u32.u64 %0, t; }" : "=r"(a) : "l"(p));
    return a;
}
__device__ __forceinline__ void ldmx4(uint32_t& r0, uint32_t& r1, uint32_t& r2, uint32_t& r3,
                                      uint32_t a) {
    asm volatile("ldmatrix.sync.aligned.m8n8.x4.shared.b16 {%0,%1,%2,%3}, [%4];"
                 : "=r"(r0), "=r"(r1), "=r"(r2), "=r"(r3) : "r"(a));
}
__device__ __forceinline__ void mma4(float c[4], uint32_t a0, uint32_t a1, uint32_t a2,
                                     uint32_t a3, uint32_t b0, uint32_t b1) {
    asm volatile("mma.sync.aligned.m16n8k16.row.col.f32.f16.f16.f32 "
                 "{%0,%1,%2,%3},{%4,%5,%6,%7},{%8,%9},{%0,%1,%2,%3};"
                 : "+f"(c[0]), "+f"(c[1]), "+f"(c[2]), "+f"(c[3])
                 : "r"(a0), "r"(a1), "r"(a2), "r"(a3), "r"(b0), "r"(b1));
}
__device__ __forceinline__ uint32_t afa(uint32_t base, int lane, int mrow, int kb, int sh) {
    int row = mrow + (lane & 15);
    int k = kb + ((lane >> 4) << 3);
    return base + (uint32_t)(row * sh + k) * 2;
}
__device__ __forceinline__ uint32_t bfa(uint32_t base, int lane, int nb, int kb, int sh) {
    int n = nb + (lane & 7) + ((lane >> 4) << 3);
    int k = kb + (((lane >> 3) & 1) << 3);
    return base + (uint32_t)(n * sh + k) * 2;
}
__device__ __forceinline__ void red4(float* p, float4 v) {
    asm volatile("red.global.add.v4.f32 [%0], {%1,%2,%3,%4};"
                 :: "l"(p), "f"(v.x), "f"(v.y), "f"(v.z), "f"(v.w) : "memory");
}
__device__ __forceinline__ void mma_pair(float Ce[4], float Co[4],
    uint32_t ah0,uint32_t ah1,uint32_t ah2,uint32_t ah3,
    uint32_t al0,uint32_t al1,uint32_t al2,uint32_t al3,
    uint32_t bh0,uint32_t bh1,uint32_t bh2,uint32_t bh3,
    uint32_t bl0,uint32_t bl1,uint32_t bl2,uint32_t bl3)
{
    mma4(Ce, ah0, ah1, ah2, ah3, bh0, bh1);
    mma4(Co, ah0, ah1, ah2, ah3, bh2, bh3);
    mma4(Ce, al0, al1, al2, al3, bh0, bh1);
    mma4(Co, al0, al1, al2, al3, bh2, bh3);
    mma4(Ce, ah0, ah1, ah2, ah3, bl0, bl1);
    mma4(Co, ah0, ah1, ah2, ah3, bl2, bl3);
}
__device__ __forceinline__ void cvt4(__half* Hp, __half* Lp, int idx, float4 v) {
    __half h0 = __float2half_rn(v.x), h1 = __float2half_rn(v.y);
    __half h2 = __float2half_rn(v.z), h3 = __float2half_rn(v.w);
    ((__half2*)(Hp + idx))[0] = __halves2half2(h0, h1);
    ((__half2*)(Hp + idx))[1] = __halves2half2(h2, h3);
    ((__half2*)(Lp + idx))[0] = __halves2half2(__float2half_rn(v.x - __half2float(h0)),
                                               __float2half_rn(v.y - __half2float(h1)));
    ((__half2*)(Lp + idx))[1] = __halves2half2(__float2half_rn(v.z - __half2float(h2)),
                                               __float2half_rn(v.w - __half2float(h3)));
}

// ---------------- launch 0: weight prep + rcv histogram -------------------------
__global__ void prep_all(const float* W_up, const float* Wl0, const float* Wl1,
                         const float* Wl2, const float* P0, const float* P1,
                         const float* Wr1, const float* Wr2,
                         const float* W1, const float* W2,
                         const int* edge_index, int E)
{
    int w = blockIdx.y;
    if (w == 10) {
        for (int e = blockIdx.x * blockDim.x + threadIdx.x; e < E;
             e += gridDim.x * blockDim.x)
            atomicAdd(&g_cnt[edge_index[E + e]], 1);
        return;
    }
    const float* src; __half* dst; int K, Nr, ldw, stride; float sc = 1.f;
    const int TS = 2 * 128 * 136;
    switch (w) {
        case 0: src = W_up; dst = g_wt;        K=128; Nr=128; ldw=128; stride=136; break;
        case 1: src = Wl0;  dst = g_wt + 1*TS; K=128; Nr=128; ldw=128; stride=136; break;
        case 2: src = Wl1;  dst = g_wt + 2*TS; K=128; Nr=128; ldw=128; stride=136; break;
        case 3: src = Wl2;  dst = g_wt + 3*TS; K=128; Nr=128; ldw=128; stride=136; break;
        case 4: src = P0;   dst = g_wt + 4*TS; K=128; Nr=128; ldw=128; stride=136; break;
        case 5: src = P1;   dst = g_wt + 5*TS; K=128; Nr=128; ldw=128; stride=136; break;
        case 6: src = Wr1;  dst = g_wr1t;      K=128; Nr= 64; ldw= 64; stride=136; break;
        case 7: src = Wr2;  dst = g_wr2t;      K= 64; Nr=384; ldw=384; stride= 72;
                sc = 0.0625f; break;   // fold 1/AVG into Wr2
        case 8: src = W1;   dst = g_w1t;       K=128; Nr= 64; ldw= 64; stride=136; break;
        default:src = W2;   dst = g_w2t;       K= 64; Nr=128; ldw=128; stride= 72; break;
    }
    int i = blockIdx.x * blockDim.x + threadIdx.x;
    if (i >= K * Nr) return;
    int n = i / K, k = i % K;
    float v = src[(size_t)k * ldw + n] * sc;
    __half h = __float2half_rn(v);
    dst[(size_t)n * stride + k] = h;
    dst[(size_t)Nr * stride + (size_t)n * stride + k] = __float2half_rn(v - __half2float(h));
}

// ---------------- launch 1: exclusive scan (3-phase, 2 barriers) -----------------
__global__ void scan_k(int N)
{
    __shared__ int wsum[32];
    int t = threadIdx.x;
    int lane = t & 31, wid = t >> 5;
    int chunk = (N + 1023) >> 10;          // 10 for N=10000
    int base = t * chunk;

    // phase 1: thread-serial chunk total
    int s = 0;
    for (int i = 0; i < chunk; i++) {
        int idx = base + i;
        if (idx < N) s += g_cnt[idx];
    }
    // phase 2: warp inclusive scan of chunk totals
    int x = s;
#pragma unroll
    for (int off = 1; off < 32; off <<= 1) {
        int y = __shfl_up_sync(0xffffffffu, x, off);
        if (lane >= off) x += y;
    }
    if (lane == 31) wsum[wid] = x;          // warp total (inclusive of last)
    __syncthreads();
    if (t < 32) {
        int w = wsum[t];
        int inc = w;
#pragma unroll
        for (int off = 1; off < 32; off <<= 1) {
            int y = __shfl_up_sync(0xffffffffu, inc, off);
            if (t >= off) inc += y;
        }
        wsum[t] = inc - w;                  // exclusive warp offset
    }
    __syncthreads();
    // phase 3: write back exclusive prefixes
    int run = wsum[wid] + (x - s);          // thread's exclusive base
    for (int i = 0; i < chunk; i++) {
        int idx = base + i;
        if (idx < N) {
            int v = g_cnt[idx];
            g_cnt[idx] = run;
            run += v;
        }
    }
}

// ---------------- node-GEMM: 64-row tiles, 2-D warp tiling, 104.4KB, 2 CTA/SM ----
__device__ __forceinline__ void node_gemm(float* A, float* O, int M, int tile,
                                          int tiles, char* smem, int clearA,
                                          int bx, int gx)
{
    __half* Ah = (__half*)smem;
    __half* Al = (__half*)(smem + 17408);
    uint32_t sb = s2u(smem);
    int tid = threadIdx.x, wid = tid >> 5, lane = tid & 31;
    int rw = wid & 3, cw = wid >> 2;
    int mrow = rw * 16;

    {   const uint4* s = (const uint4*)(g_wt + (size_t)tile * (2*128*136));
        uint4* d = (uint4*)(smem + 34816);
        for (int i = tid; i < 4352; i += 256) d[i] = s[i];
    }
    uint32_t ab_h = sb, ab_l = sb + 17408, bb_h = sb + 34816, bb_l = sb + 69632;
    int rr = tid >> 2, q4 = tid & 3;

    for (int tl = bx; tl < tiles; tl += gx) {
        int bm = tl * 64;
        bool valid = (bm + rr) < M;
        float* Arow = A + (size_t)(bm + rr) * 128;
        {
#pragma unroll
            for (int q = 0; q < 8; q++) {
                float4 v = valid ? ((const float4*)Arow)[q4 * 8 + q]
                                 : make_float4(0.f, 0.f, 0.f, 0.f);
                cvt4(Ah, Al, rr * 136 + q4 * 32 + q * 4, v);
            }
            if (clearA && valid) {
                float4 z = make_float4(0.f, 0.f, 0.f, 0.f);
#pragma unroll
                for (int q = 0; q < 8; q++) ((float4*)Arow)[q4 * 8 + q] = z;
            }
        }
        __syncthreads();

        float C[8][4];
#pragma unroll
        for (int i = 0; i < 8; i++)
#pragma unroll
            for (int j = 0; j < 4; j++) C[i][j] = 0.f;

        for (int kb = 0; kb < 128; kb += 16) {
            uint32_t ah0, ah1, ah2, ah3, al0, al1, al2, al3;
            ldmx4(ah0, ah1, ah2, ah3, afa(ab_h, lane, mrow, kb, 136));
            ldmx4(al0, al1, al2, al3, afa(ab_l, lane, mrow, kb, 136));
#pragma unroll
            for (int nt2 = 0; nt2 < 4; nt2++) {
                uint32_t bh0, bh1, bh2, bh3, bl0, bl1, bl2, bl3;
                int nb = cw * 64 + nt2 * 16;
                ldmx4(bh0, bh1, bh2, bh3, bfa(bb_h, lane, nb, kb, 136));
                ldmx4(bl0, bl1, bl2, bl3, bfa(bb_l, lane, nb, kb, 136));
                mma_pair(C[2*nt2], C[2*nt2+1], ah0,ah1,ah2,ah3, al0,al1,al2,al3,
                         bh0,bh1,bh2,bh3, bl0,bl1,bl2,bl3);
            }
        }

        int r0 = bm + mrow + (lane >> 2);
        int c0 = cw * 64 + (lane & 3) * 2;
        bool v0 = r0 < M, v1 = (r0 + 8) < M;
#pragma unroll
        for (int nt = 0; nt < 8; nt++) {
            int col = c0 + nt * 8;
            if (v0) *(float2*)(O + (size_t)r0 * 128 + col) = make_float2(C[nt][0], C[nt][1]);
            if (v1) *(float2*)(O + (size_t)(r0 + 8) * 128 + col) = make_float2(C[nt][2], C[nt][3]);
        }
        __syncthreads();
    }
}

// ---------------- launch 2: y0 = permutation scatter, y1 = h GEMM ---------------
__global__ void __launch_bounds__(256, 2)
permh(const int* __restrict__ edge_index, const float* __restrict__ node_feats,
      int E, int M, int mt)
{
    extern __shared__ char smem[];
    if (blockIdx.y == 0) {
        for (int e = blockIdx.x * blockDim.x + threadIdx.x; e < E;
             e += gridDim.x * blockDim.x) {
            int rcv = edge_index[E + e];
            int pos = atomicAdd(&g_cnt[rcv], 1);
            g_perm[pos] = e;
        }
        return;
    }
    node_gemm((float*)node_feats, g_h, M, 0, mt, smem, 0, blockIdx.x, gridDim.x);
}

// ---------------- launches 4/6: svt = agg@Wl (clears agg), hout = B@P -----------
__global__ void __launch_bounds__(256, 2)
mma128(float* __restrict__ A0, float* __restrict__ O0, int M, int phase, int mt)
{
    extern __shared__ char smem[];
    int comp = blockIdx.y;
    int tile = (phase == 1) ? ((comp == 0) ? 1 : (comp < 4 ? 2 : 3))
                            : ((comp == 0) ? 4 : 5);
    node_gemm(A0 + (size_t)comp * M * 128, O0 + (size_t)comp * M * 128,
              M, tile, mt, smem, phase == 1, blockIdx.x, gridDim.x);
}

// ---------------- launch 3: fused edge kernel, 64 edges, 72.96KB -> 3 CTA/SM -----
__global__ void __launch_bounds__(256, 3)
edge_fused(const float* __restrict__ vectors, const int* __restrict__ edge_index,
           const float* __restrict__ edge_feats, const float* __restrict__ lengths,
           const float* __restrict__ wlast, const float* __restrict__ bias,
           int E, int N)
{
    extern __shared__ char smc[];
    uint32_t sb = s2u(smc);
    __half* efAh = (__half*)smc;
    __half* efAl = (__half*)(smc + 17408);
    float* wl_sm = (float*)(smc + 69632);
    float* b_sm  = (float*)(smc + 69888);
    float* Ys    = (float*)(smc + 70144);
    int* snd_s   = (int*)(smc + 72192);
    int* rcv_s   = (int*)(smc + 72448);
    float* len_s = (float*)(smc + 72704);
    float* stage = (float*)(smc + 18432);
    int tid = threadIdx.x, wid = tid >> 5, lane = tid & 31;
    int e0 = blockIdx.x * 64;
    int rw = wid & 3, cw = wid >> 2;
    int mrow = rw * 16;

    if (tid < 64) { wl_sm[tid] = wlast[tid]; b_sm[tid] = bias[tid]; }
    {   const uint4* s = (const uint4*)g_wr1t;
        uint4* d = (uint4*)(smc + 34816);
        for (int i = tid; i < 2176; i += 256) d[i] = s[i];
    }
    {   int r = tid >> 2, q4 = tid & 3;
        bool valid = (e0 + r) < E;
        const float* Arow = edge_feats + (valid ? (size_t)g_perm[e0 + r] * 128 : 0);
#pragma unroll
        for (int q = 0; q < 8; q++) {
            float4 v = valid ? ((const float4*)Arow)[q4 * 8 + q]
                             : make_float4(0.f, 0.f, 0.f, 0.f);
            cvt4(efAh, efAl, r * 136 + q4 * 32 + q * 4, v);
        }
    }
    if (tid < 64) {
        int e = e0 + tid;
        int snd = 0, rcv = 0;
        float vx = 0.f, vy = 1.f, vz = 0.f, ln = 0.f;
        if (e < E) {
            int pe = g_perm[e];
            snd = edge_index[pe]; rcv = edge_index[E + pe];
            vx = vectors[3*pe]; vy = vectors[3*pe+1]; vz = vectors[3*pe+2];
            ln = lengths[pe];
        }
        snd_s[tid] = snd; rcv_s[tid] = rcv; len_s[tid] = ln;
        float inv = 1.f / (sqrtf(vx*vx + vy*vy + vz*vz) + 1e-9f);
        float ux = vx*inv, uy = vy*inv, uz = vz*inv;
        const float S3 = 1.7320508075688772f, S15 = 3.8729833462074170f;
        const float S15H = 1.9364916731037085f, S5H = 1.1180339887498949f;
        float* y = Ys + tid * 8;
        y[0] = S3*ux; y[1] = S3*uy; y[2] = S3*uz;
        y[3] = S15*ux*uy; y[4] = S15*uy*uz; y[5] = S5H*(3.f*uz*uz - 1.f);
        y[6] = S15*ux*uz; y[7] = S15H*(ux*ux - uy*uy);
    }
    __syncthreads();

    // radial MMA: z = ef @ Wr1
    float Cz[4][4];
#pragma unroll
    for (int i = 0; i < 4; i++)
#pragma unroll
        for (int j = 0; j < 4; j++) Cz[i][j] = 0.f;
    {
        uint32_t ab_h = sb, ab_l = sb + 17408, bb_h = sb + 34816, bb_l = sb + 52224;
        for (int kb = 0; kb < 128; kb += 16) {
            uint32_t ah0, ah1, ah2, ah3, al0, al1, al2, al3;
            ldmx4(ah0, ah1, ah2, ah3, afa(ab_h, lane, mrow, kb, 136));
            ldmx4(al0, al1, al2, al3, afa(ab_l, lane, mrow, kb, 136));
#pragma unroll
            for (int nt2 = 0; nt2 < 2; nt2++) {
                uint32_t bh0, bh1, bh2, bh3, bl0, bl1, bl2, bl3;
                int nb = cw * 32 + nt2 * 16;
                ldmx4(bh0, bh1, bh2, bh3, bfa(bb_h, lane, nb, kb, 136));
                ldmx4(bl0, bl1, bl2, bl3, bfa(bb_l, lane, nb, kb, 136));
                mma_pair(Cz[2*nt2], Cz[2*nt2+1], ah0,ah1,ah2,ah3, al0,al1,al2,al3,
                         bh0,bh1,bh2,bh3, bl0,bl1,bl2,bl3);
            }
        }
    }
    __syncthreads();

    // epilogue: silu -> z hi/lo smem (stride 72)
    {
        int r0 = mrow + (lane >> 2);
        int c0 = cw * 32 + (lane & 3) * 2;
        float len0 = len_s[r0];
        float len1 = len_s[r0 + 8];
#pragma unroll
        for (int nt = 0; nt < 4; nt++) {
            int col = c0 + nt * 8;
            float wl0 = wl_sm[col], wl1 = wl_sm[col + 1];
            float bb0 = b_sm[col],  bb1 = b_sm[col + 1];
            float f0 = Cz[nt][0] + len0 * wl0 + bb0;
            float f1 = Cz[nt][1] + len0 * wl1 + bb1;
            float f2 = Cz[nt][2] + len1 * wl0 + bb0;
            float f3 = Cz[nt][3] + len1 * wl1 + bb1;
            f0 = f0 / (1.f + __expf(-f0));
            f1 = f1 / (1.f + __expf(-f1));
            f2 = f2 / (1.f + __expf(-f2));
            f3 = f3 / (1.f + __expf(-f3));
            __half h0 = __float2half_rn(f0), h1 = __float2half_rn(f1);
            __half h2 = __float2half_rn(f2), h3 = __float2half_rn(f3);
            *(__half2*)(smc + r0 * 144 + col * 2) = __halves2half2(h0, h1);
            *(__half2*)(smc + (r0 + 8) * 144 + col * 2) = __halves2half2(h2, h3);
            *(__half2*)(smc + 9216 + r0 * 144 + col * 2) =
                __halves2half2(__float2half_rn(f0 - __half2float(h0)),
                               __float2half_rn(f1 - __half2float(h1)));
            *(__half2*)(smc + 9216 + (r0 + 8) * 144 + col * 2) =
                __halves2half2(__float2half_rn(f2 - __half2float(h2)),
                               __float2half_rn(f3 - __half2float(h3)));
        }
    }

    uint32_t zb_h = sb, zb_l = sb + 9216;
    const float4* h4g = (const float4*)g_h;
    int NC = N * CC;

    for (int l = 0; l < 3; l++) {
        __syncthreads();
        {   const uint4* sh4 = (const uint4*)g_wr2t + (size_t)l * 1152;
            const uint4* sl4 = (const uint4*)g_wr2t + 3456 + (size_t)l * 1152;
            uint4* dh = (uint4*)(smc + 18432);
            uint4* dl = (uint4*)(smc + 36864);
            for (int i = tid; i < 1152; i += 256) { dh[i] = sh4[i]; dl[i] = sl4[i]; }
        }
        __syncthreads();

        uint32_t wb_h = sb + 18432, wb_l = sb + 36864;
        float C[8][4];
#pragma unroll
        for (int i = 0; i < 8; i++)
#pragma unroll
            for (int j = 0; j < 4; j++) C[i][j] = 0.f;

        for (int kb = 0; kb < 64; kb += 16) {
            uint32_t ah0, ah1, ah2, ah3, al0, al1, al2, al3;
            ldmx4(ah0, ah1, ah2, ah3, afa(zb_h, lane, mrow, kb, 72));
            ldmx4(al0, al1, al2, al3, afa(zb_l, lane, mrow, kb, 72));
#pragma unroll
            for (int nt2 = 0; nt2 < 4; nt2++) {
                uint32_t bh0, bh1, bh2, bh3, bl0, bl1, bl2, bl3;
                int nb = cw * 64 + nt2 * 16;
                ldmx4(bh0, bh1, bh2, bh3, bfa(wb_h, lane, nb, kb, 72));
                ldmx4(bl0, bl1, bl2, bl3, bfa(wb_l, lane, nb, kb, 72));
                mma_pair(C[2*nt2], C[2*nt2+1], ah0,ah1,ah2,ah3, al0,al1,al2,al3,
                         bh0,bh1,bh2,bh3, bl0,bl1,bl2,bl3);
            }
        }
        __syncthreads();

        {   int r0 = mrow + (lane >> 2);
            int c0 = cw * 64 + (lane & 3) * 2;
#pragma unroll
            for (int nt = 0; nt < 8; nt++) {
                int col = c0 + nt * 8;
                *(float2*)(stage + r0 * 132 + col) = make_float2(C[nt][0], C[nt][1]);
                *(float2*)(stage + (r0 + 8) * 132 + col) = make_float2(C[nt][2], C[nt][3]);
            }
        }
        __syncthreads();

        {   // run-merged scatter, warp owns 8 edges, red4
            int base = wid * 8;
            int cnt = E - e0 - base; if (cnt > 8) cnt = 8;
            if (cnt > 0) {
                int nc = (l == 0) ? 1 : ((l == 1) ? 3 : 5);
                int co = (l == 0) ? 0 : ((l == 1) ? 1 : 4);
                float4 acc[5];
#pragma unroll
                for (int m = 0; m < 5; m++) acc[m] = make_float4(0.f, 0.f, 0.f, 0.f);
                int cur = rcv_s[base];
                float4 hv = h4g[(size_t)snd_s[base] * 32 + lane];
                float4 rv = *(const float4*)(stage + base * 132 + lane * 4);
                for (int j = 0; j < cnt; j++) {
                    int el = base + j;
                    float4 hv_n = hv, rv_n = rv;
                    if (j + 1 < cnt) {
                        hv_n = h4g[(size_t)snd_s[el + 1] * 32 + lane];
                        rv_n = *(const float4*)(stage + (el + 1) * 132 + lane * 4);
                    }
                    int rcv = rcv_s[el];
                    if (rcv != cur) {
                        float* bp = g_agg + (size_t)co * NC + (size_t)cur * CC + lane * 4;
                        for (int m = 0; m < nc; m++) {
                            red4(bp, acc[m]);
                            bp += NC;
                            acc[m] = make_float4(0.f, 0.f, 0.f, 0.f);
                        }
                        cur = rcv;
                    }
                    float cx = hv.x * rv.x, cy = hv.y * rv.y;
                    float cz = hv.z * rv.z, cw4 = hv.w * rv.w;
#pragma unroll
                    for (int m = 0; m < 5; m++) {
                        if (m >= nc) break;
                        float y = (l == 0) ? 1.f
                                : (l == 1) ? Ys[el * 8 + m]
                                           : Ys[el * 8 + 3 + m];
                        acc[m].x += cx * y; acc[m].y += cy * y;
                        acc[m].z += cz * y; acc[m].w += cw4 * y;
                    }
                    hv = hv_n; rv = rv_n;
                }
                float* bp = g_agg + (size_t)co * NC + (size_t)cur * CC + lane * 4;
                for (int m = 0; m < nc; m++) { red4(bp, acc[m]); bp += NC; }
            }
        }
    }
}

// ---------------- launch 7: fused readout ----------------------------------------
__global__ void __launch_bounds__(256, 3)
readout_k(const float* __restrict__ W3, const float* __restrict__ b1,
          float* __restrict__ out, int N)
{
    extern __shared__ char smc[];
    uint32_t sb = s2u(smc);
    __half* Ah = (__half*)smc;
    __half* Al = (__half*)(smc + 17408);
    float* zf   = (float*)(smc + 55296);
    float* W3sm = (float*)(smc + 71680);
    float* b1sm = (float*)(smc + 71936);
    int tid = threadIdx.x, wid = tid >> 5, lane = tid & 31;
    int bm = blockIdx.x * 64;
    int rw = wid & 3, cw = wid >> 2;
    int mrow = rw * 16;

    if (tid < 64) { W3sm[tid] = W3[tid]; b1sm[tid] = b1[tid]; }
    {   const uint4* s = (const uint4*)g_w1t;
        uint4* d = (uint4*)(smc + 34816);
        for (int i = tid; i < 2176; i += 256) d[i] = s[i];
    }
    {   int r = tid >> 2, q4 = tid & 3;
        bool valid = (bm + r) < N;
        const float* Arow = g_hout + (size_t)(bm + r) * 128;
#pragma unroll
        for (int q = 0; q < 8; q++) {
            float4 v = valid ? ((const float4*)Arow)[q4 * 8 + q]
                             : make_float4(0.f, 0.f, 0.f, 0.f);
            cvt4(Ah, Al, r * 136 + q4 * 32 + q * 4, v);
        }
    }
    __syncthreads();

    float Cz[4][4];
#pragma unroll
    for (int i = 0; i < 4; i++)
#pragma unroll
        for (int j = 0; j < 4; j++) Cz[i][j] = 0.f;
    {
        uint32_t ab_h = sb, ab_l = sb + 17408, bb_h = sb + 34816, bb_l = sb + 52224;
        for (int kb = 0; kb < 128; kb += 16) {
            uint32_t ah0, ah1, ah2, ah3, al0, al1, al2, al3;
            ldmx4(ah0, ah1, ah2, ah3, afa(ab_h, lane, mrow, kb, 136));
            ldmx4(al0, al1, al2, al3, afa(ab_l, lane, mrow, kb, 136));
#pragma unroll
            for (int nt2 = 0; nt2 < 2; nt2++) {
                uint32_t bh0, bh1, bh2, bh3, bl0, bl1, bl2, bl3;
                int nb = cw * 32 + nt2 * 16;
                ldmx4(bh0, bh1, bh2, bh3, bfa(bb_h, lane, nb, kb, 136));
                ldmx4(bl0, bl1, bl2, bl3, bfa(bb_l, lane, nb, kb, 136));
                mma_pair(Cz[2*nt2], Cz[2*nt2+1], ah0,ah1,ah2,ah3, al0,al1,al2,al3,
                         bh0,bh1,bh2,bh3, bl0,bl1,bl2,bl3);
            }
        }
    }
    __syncthreads();

    {
        int r0 = mrow + (lane >> 2);
        int c0 = cw * 32 + (lane & 3) * 2;
#pragma unroll
        for (int nt = 0; nt < 4; nt++) {
            int col = c0 + nt * 8;
            float f0 = Cz[nt][0] + b1sm[col];
            float f1 = Cz[nt][1] + b1sm[col + 1];
            float f2 = Cz[nt][2] + b1sm[col];
            float f3 = Cz[nt][3] + b1sm[col + 1];
            f0 = f0 / (1.f + __expf(-f0));
            f1 = f1 / (1.f + __expf(-f1));
            f2 = f2 / (1.f + __expf(-f2));
            f3 = f3 / (1.f + __expf(-f3));
            __half h0 = __float2half_rn(f0), h1 = __float2half_rn(f1);
            __half h2 = __float2half_rn(f2), h3 = __float2half_rn(f3);
            *(__half2*)(smc + r0 * 144 + col * 2) = __halves2half2(h0, h1);
            *(__half2*)(smc + (r0 + 8) * 144 + col * 2) = __halves2half2(h2, h3);
            *(__half2*)(smc + 9216 + r0 * 144 + col * 2) =
                __halves2half2(__float2half_rn(f0 - __half2float(h0)),
                               __float2half_rn(f1 - __half2float(h1)));
            *(__half2*)(smc + 9216 + (r0 + 8) * 144 + col * 2) =
                __halves2half2(__float2half_rn(f2 - __half2float(h2)),
                               __float2half_rn(f3 - __half2float(h3)));
            zf[r0 * 64 + col] = f0; zf[r0 * 64 + col + 1] = f1;
            zf[(r0 + 8) * 64 + col] = f2; zf[(r0 + 8) * 64 + col + 1] = f3;
        }
    }
    __syncthreads();

    {   const uint4* s = (const uint4*)g_w2t;
        uint4* d = (uint4*)(smc + 18432);
        for (int i = tid; i < 2304; i += 256) d[i] = s[i];
    }
    __syncthreads();

    uint32_t zb_h = sb, zb_l = sb + 9216;
    uint32_t wb_h = sb + 18432, wb_l = sb + 36864;
    float C[8][4];
#pragma unroll
    for (int i = 0; i < 8; i++)
#pragma unroll
        for (int j = 0; j < 4; j++) C[i][j] = 0.f;

    for (int kb = 0; kb < 64; kb += 16) {
        uint32_t ah0, ah1, ah2, ah3, al0, al1, al2, al3;
        ldmx4(ah0, ah1, ah2, ah3, afa(zb_h, lane, mrow, kb, 72));
        ldmx4(al0, al1, al2, al3, afa(zb_l, lane, mrow, kb, 72));
#pragma unroll
        for (int nt2 = 0; nt2 < 4; nt2++) {
            uint32_t bh0, bh1, bh2, bh3, bl0, bl1, bl2, bl3;
            int nb = cw * 64 + nt2 * 16;
            ldmx4(bh0, bh1, bh2, bh3, bfa(wb_h, lane, nb, kb, 72));
            ldmx4(bl0, bl1, bl2, bl3, bfa(wb_l, lane, nb, kb, 72));
            mma_pair(C[2*nt2], C[2*nt2+1], ah0,ah1,ah2,ah3, al0,al1,al2,al3,
                     bh0,bh1,bh2,bh3, bl0,bl1,bl2,bl3);
        }
    }
    {   int r0 = bm + mrow + (lane >> 2);
        int c0 = cw * 64 + (lane & 3) * 2;
        bool v0 = r0 < N, v1 = (r0 + 8) < N;
#pragma unroll
        for (int nt = 0; nt < 8; nt++) {
            int col = c0 + nt * 8;
            if (v0) *(float2*)(out + (size_t)r0 * 128 + col) = make_float2(C[nt][0], C[nt][1]);
            if (v1) *(float2*)(out + (size_t)(r0 + 8) * 128 + col) = make_float2(C[nt][2], C[nt][3]);
        }
    }
    {   int nd = tid >> 2, t4 = tid & 3;
        float p = 0.f;
        if (bm + nd < N) {
#pragma unroll
            for (int d = 0; d < 16; d++)
                p = fmaf(zf[nd * 64 + t4 * 16 + d], W3sm[t4 * 16 + d], p);
        }
        p += __shfl_xor_sync(0xffffffffu, p, 1);
        p += __shfl_xor_sync(0xffffffffu, p, 2);
        if (t4 == 0 && bm + nd < N) g_zr[bm + nd] = p;
    }
}

// ---------------- symmetric contraction ----------------------------------------
__global__ void contract_k(const float* __restrict__ w0, const float* __restrict__ w1, int N)
{
    int i = blockIdx.x * blockDim.x + threadIdx.x;
    int NC = N * CC;
    if (i >= NC) return;
    int c = i & (CC - 1);
    const float* svt = g_svt;
    float* Bv = g_B;

    float s  = svt[i];
    float vx = svt[NC + i], vy = svt[2*NC + i], vz = svt[3*NC + i];
    float ta = svt[4*NC + i], tb = svt[5*NC + i], tcm = svt[6*NC + i];
    float td = svt[7*NC + i], te = svt[8*NC + i];

    float c3 = tcm * 0.5773502691896258f;
    float Txx = te - c3, Txy = ta, Txz = td;
    float Tyy = -te - c3, Tyz = tb;
    float Tzz = 2.f * c3;

    float v2 = vx*vx + vy*vy + vz*vz;
    float t2 = ta*ta + tb*tb + tcm*tcm + td*td + te*te;
    float Tvx = Txx*vx + Txy*vy + Txz*vz;
    float Tvy = Txy*vx + Tyy*vy + Tyz*vz;
    float Tvz = Txz*vx + Tyz*vy + Tzz*vz;
    float vTv = vx*Tvx + vy*Tvy + vz*Tvz;

    float B0 = w0[c]*s + w0[CC+c]*s*s + w0[2*CC+c]*v2 + w0[3*CC+c]*t2
             + w0[4*CC+c]*s*s*s + w0[5*CC+c]*s*v2 + w0[6*CC+c]*s*t2 + w0[7*CC+c]*vTv;

    float k0 = w1[c], k1 = w1[CC+c], k2 = w1[2*CC+c];
    float k3 = w1[3*CC+c], k4 = w1[4*CC+c], k5 = w1[5*CC+c];
    float f = k0 + k1*s + k3*s*s + k4*v2;
    float gT = k2 + k5*s;

    Bv[i] = B0;
    Bv[NC + i]   = f*vx + gT*Tvx;
    Bv[2*NC + i] = f*vy + gT*Tvy;
    Bv[3*NC + i] = f*vz + gT*Tvz;
}

// ---------------- finalize (gate precomputed; also re-zeros histogram) -----------
__global__ void final_k(const float* __restrict__ wv, float* __restrict__ out, int N)
{
    int gt = blockIdx.x * blockDim.x + threadIdx.x;
    if (gt <= NN) g_cnt[gt] = 0;
    int lane = threadIdx.x & 31;
    int node = gt >> 5;
    if (node >= N) return;
    int NC = N * CC;
    const float* h0 = g_hout;
    const float* h1 = g_hout + NC;

    float gate = g_zr[node];
    float sx = 0.f, sy = 0.f, sz = 0.f;
#pragma unroll
    for (int c = lane; c < CC; c += 32) {
        float w = wv[c];
        sx = fmaf(h1[node*CC + c], w, sx);
        sy = fmaf(h1[NC + node*CC + c], w, sy);
        sz = fmaf(h1[2*NC + node*CC + c], w, sz);
    }
#pragma unroll
    for (int off = 16; off; off >>= 1) {
        sx += __shfl_xor_sync(0xffffffffu, sx, off);
        sy += __shfl_xor_sync(0xffffffffu, sy, off);
        sz += __shfl_xor_sync(0xffffffffu, sz, off);
    }
    if (lane == 0) {
        float* ov = out + (size_t)N * 128 + (size_t)node * 3;
        ov[0] = sx * gate; ov[1] = sy * gate; ov[2] = sz * gate;
    }
    float* nf = out + (size_t)N * 131 + (size_t)node * 512;
#pragma unroll
    for (int c = lane; c < CC; c += 32) {
        nf[c] = h0[node*CC + c];
        nf[128 + 3*c + 0] = h1[node*CC + c];
        nf[128 + 3*c + 1] = h1[NC + node*CC + c];
        nf[128 + 3*c + 2] = h1[2*NC + node*CC + c];
    }
}

// ---------------- host launcher --------------------------------------------------
extern "C" void kernel_launch(void* const* d_in, const int* in_sizes, int n_in,
                              void* d_out, int out_size)
{
    const float* vectors    = (const float*)d_in[0];
    const float* lengths    = (const float*)d_in[1];
    const float* node_feats = (const float*)d_in[2];
    const float* edge_feats = (const float*)d_in[3];
    const int*   edge_index = (const int*)  d_in[4];
    const float* W_up = (const float*)d_in[5];
    const float* Wr1  = (const float*)d_in[6];
    const float* br1  = (const float*)d_in[7];
    const float* Wr2  = (const float*)d_in[8];
    const float* Wl0  = (const float*)d_in[9];
    const float* Wl1  = (const float*)d_in[10];
    const float* Wl2  = (const float*)d_in[11];
    const float* w0   = (const float*)d_in[12];
    const float* w1   = (const float*)d_in[13];
    const float* P0   = (const float*)d_in[14];
    const float* P1   = (const float*)d_in[15];
    const float* W1   = (const float*)d_in[16];
    const float* b1   = (const float*)d_in[17];
    const float* W2   = (const float*)d_in[18];
    const float* W3   = (const float*)d_in[19];
    const float* wv   = (const float*)d_in[20];
    float* out = (float*)d_out;

    int E = in_sizes[1];
    int N = in_sizes[2] / CC;
    int NC = N * CC;

    float *p_agg, *p_svt, *p_B, *p_hout;
    cudaGetSymbolAddress((void**)&p_agg,  g_agg);
    cudaGetSymbolAddress((void**)&p_svt,  g_svt);
    cudaGetSymbolAddress((void**)&p_B,    g_B);
    cudaGetSymbolAddress((void**)&p_hout, g_hout);

    int mt64 = (N + 63) / 64;
    const int SM_G = 104448;   // node_gemm: 2 CTA/SM
    const int SM_E = 72960;    // edge_fused: 3 CTA/SM
    const int SM_R = 72192;    // readout: 3 CTA/SM
    cudaFuncSetAttribute(mma128, cudaFuncAttributeMaxDynamicSharedMemorySize, SM_G);
    cudaFuncSetAttribute(permh, cudaFuncAttributeMaxDynamicSharedMemorySize, SM_G);
    cudaFuncSetAttribute(edge_fused, cudaFuncAttributeMaxDynamicSharedMemorySize, SM_E);
    cudaFuncSetAttribute(readout_k, cudaFuncAttributeMaxDynamicSharedMemorySize, SM_R);

    // 0: weight prep + rcv histogram
    prep_all<<<dim3(96, 11), 256>>>(W_up, Wl0, Wl1, Wl2, P0, P1, Wr1, Wr2,
                                    W1, W2, edge_index, E);
    // 1: exclusive scan (fast 3-phase)
    scan_k<<<1, 1024>>>(N);
    // 2: perm scatter (y=0) + h = nf@W_up (y=1)
    permh<<<dim3(160, 2), 256, SM_G>>>(edge_index, node_feats, E, N, mt64);
    // 3: fused edge kernel (ncu capture lands here)
    edge_fused<<<(E + 63) / 64, 256, SM_E>>>(vectors, edge_index, edge_feats, lengths,
                                             Wr1 + 128*64, br1, E, N);
    // 4: svt = agg @ Wl (clears agg for next run)
    mma128<<<dim3(32, 9), 256, SM_G>>>(p_agg, p_svt, N, 1, mt64);
    // 5
    contract_k<<<(NC + 255) / 256, 256>>>(w0, w1, N);
    // 6: hout = B @ P
    mma128<<<dim3(74, 4), 256, SM_G>>>(p_B, p_hout, N, 2, mt64);
    // 7: fused readout (zr, scal->out, gate)
    readout_k<<<mt64, 256, SM_R>>>(W3, b1, out, N);
    // 8: finalize + zero histogram
    final_k<<<(N * 32 + 255) / 256, 256>>>(wv, out, N);
}